// round 10
// baseline (speedup 1.0000x reference)
#include <cuda_runtime.h>
#include <cuda_fp16.h>
#include <cstdint>
#include <cstddef>

// Problem constants
#define EE   384
#define HH   6
#define HSS  64
#define BB   64
#define TT   256
#define FFD  1536
#define NROWS (BB*TT)          // 16384

// ---------------- scratch (device globals; no allocation allowed) ----------
__device__ __half g_qkv_h[(size_t)NROWS * 3 * EE];
__device__ __half g_kv_h[(size_t)NROWS * 2 * EE];
__device__ __half g_q_h[(size_t)NROWS * EE];
__device__ __half g_att_h[(size_t)NROWS * EE];
__device__ __half g_hid_h[(size_t)NROWS * FFD];
__device__ __half g_xh[(size_t)NROWS * EE];
__device__ __half g_ench[(size_t)NROWS * EE];
__device__ __half g_po1h[(size_t)NROWS * EE];
__device__ __half g_po2h[(size_t)NROWS * EE];
__device__ float  g_buf[(size_t)NROWS * EE];
__device__ float  g_o1[(size_t)NROWS * EE];
__device__ float  g_o2[(size_t)NROWS * EE];
// fp16 weights, transposed to [out][in]
__device__ __half g_wqkvh[3 * EE * EE];
__device__ __half g_wq2h[EE * EE];
__device__ __half g_wkvh[2 * EE * EE];
__device__ __half g_wp1h[EE * EE];
__device__ __half g_wp2h[EE * EE];
__device__ __half g_wf1h[FFD * EE];
__device__ __half g_wf2h[EE * FFD];
__device__ float  g_bqkv[3 * EE];
__device__ float  g_bkv[2 * EE];
__device__ float  g_bq2[EE];

// ---------------- PTX helpers ----------------------------------------------
__device__ __forceinline__ uint32_t smem_u32(const void* p) {
    uint32_t a;
    asm("{ .reg .u64 t; cvta.to.shared.u64 t, %1; cvt.u32.u64 %0, t; }" : "=r"(a) : "l"(p));
    return a;
}
__device__ __forceinline__ void cp16(uint32_t dst, const void* src) {
    asm volatile("cp.async.cg.shared.global [%0], [%1], 16;" :: "r"(dst), "l"(src));
}
__device__ __forceinline__ void ldsm4(uint32_t& r0, uint32_t& r1, uint32_t& r2, uint32_t& r3,
                                      uint32_t addr) {
    asm volatile("ldmatrix.sync.aligned.m8n8.x4.shared.b16 {%0,%1,%2,%3}, [%4];"
                 : "=r"(r0), "=r"(r1), "=r"(r2), "=r"(r3) : "r"(addr));
}
__device__ __forceinline__ void ldsm4t(uint32_t& r0, uint32_t& r1, uint32_t& r2, uint32_t& r3,
                                       uint32_t addr) {
    asm volatile("ldmatrix.sync.aligned.m8n8.x4.trans.shared.b16 {%0,%1,%2,%3}, [%4];"
                 : "=r"(r0), "=r"(r1), "=r"(r2), "=r"(r3) : "r"(addr));
}
__device__ __forceinline__ void mma16816(float* c, const uint32_t* a, const uint32_t* b) {
    asm volatile(
        "mma.sync.aligned.m16n8k16.row.col.f32.f16.f16.f32 "
        "{%0,%1,%2,%3}, {%4,%5,%6,%7}, {%8,%9}, {%0,%1,%2,%3};"
        : "+f"(c[0]), "+f"(c[1]), "+f"(c[2]), "+f"(c[3])
        : "r"(a[0]), "r"(a[1]), "r"(a[2]), "r"(a[3]), "r"(b[0]), "r"(b[1]));
}
__device__ __forceinline__ uint32_t ph2(float a, float b) {
    __half2 h = __floats2half2_rn(a, b);
    return *reinterpret_cast<uint32_t*>(&h);
}
__device__ __forceinline__ uint32_t sw_off(int r, int seg) {
    return (uint32_t)(r * 128 + (((seg ^ (r & 7)) & 7) << 4));
}

// ---------------- megapack --------------------------------------------------
#define HPK 147456
#define S_ATTNW (6*HPK)
#define S_PROJ  (2*HPK)
#define S_FF    (EE*FFD)
#define NACT    ((size_t)NROWS*EE)
#define NACTV   ((long long)(NACT/4))
#define PACK_TOTAL ((long long)S_ATTNW + S_PROJ + 2*S_FF + 3*EE + 2*EE + EE + 2*NACTV)

__global__ void megapack_kernel(
    const float* __restrict__ wq1, const float* __restrict__ wk1, const float* __restrict__ wv1,
    const float* __restrict__ wq2, const float* __restrict__ wk2, const float* __restrict__ wv2,
    const float* __restrict__ pw1, const float* __restrict__ pw2,
    const float* __restrict__ fw1, const float* __restrict__ fw2,
    const float* __restrict__ bq1, const float* __restrict__ bk1, const float* __restrict__ bv1,
    const float* __restrict__ bq2, const float* __restrict__ bk2, const float* __restrict__ bv2,
    const float* __restrict__ x, const float* __restrict__ enc,
    __half* __restrict__ wqkv, __half* __restrict__ wqo, __half* __restrict__ wkv,
    __half* __restrict__ wp1o, __half* __restrict__ wp2o,
    __half* __restrict__ wf1o, __half* __restrict__ wf2o,
    float* __restrict__ bqkv, float* __restrict__ bkv, float* __restrict__ bq2o,
    __half* __restrict__ xh, __half* __restrict__ ench)
{
    long long idx = (long long)blockIdx.x * 256 + threadIdx.x;
    if (idx >= PACK_TOTAL) return;
    const float scale = rsqrtf((float)EE);
    if (idx < S_ATTNW) {
        int reg = (int)(idx / HPK), i = (int)(idx % HPK);
        int h = i / (EE * HSS), e = (i / HSS) % EE, s = i % HSS;
        int out = h * HSS + s;
        float v; __half* dst; int rowoff;
        switch (reg) {
            case 0: v = wq1[i] * scale; dst = wqkv; rowoff = 0;      break;
            case 1: v = wk1[i];         dst = wqkv; rowoff = EE;     break;
            case 2: v = wv1[i];         dst = wqkv; rowoff = 2 * EE; break;
            case 3: v = wq2[i] * scale; dst = wqo;  rowoff = 0;      break;
            case 4: v = wk2[i];         dst = wkv;  rowoff = 0;      break;
            default: v = wv2[i];        dst = wkv;  rowoff = EE;     break;
        }
        dst[(size_t)(rowoff + out) * EE + e] = __float2half_rn(v);
        return;
    }
    idx -= S_ATTNW;
    if (idx < S_PROJ) {
        int reg = (int)(idx / HPK), i = (int)(idx % HPK);
        int e = i / EE, o = i % EE;
        (reg ? wp2o : wp1o)[(size_t)o * EE + e] = __float2half_rn((reg ? pw2 : pw1)[i]);
        return;
    }
    idx -= S_PROJ;
    if (idx < S_FF) {
        int e = (int)(idx / FFD), o = (int)(idx % FFD);
        wf1o[(size_t)o * EE + e] = __float2half_rn(fw1[idx]);
        return;
    }
    idx -= S_FF;
    if (idx < S_FF) {
        int e = (int)(idx / EE), o = (int)(idx % EE);
        wf2o[(size_t)o * FFD + e] = __float2half_rn(fw2[idx]);
        return;
    }
    idx -= S_FF;
    if (idx < 3 * EE) {
        int sub = (int)(idx / EE), jj = (int)(idx % EE);
        bqkv[idx] = sub == 0 ? bq1[jj] * scale : sub == 1 ? bk1[jj] : bv1[jj];
        return;
    }
    idx -= 3 * EE;
    if (idx < 2 * EE) { bkv[idx] = idx < EE ? bk2[idx] : bv2[idx - EE]; return; }
    idx -= 2 * EE;
    if (idx < EE) { bq2o[idx] = bq2[idx] * scale; return; }
    idx -= EE;
    const float* srcf; __half* dsth;
    if (idx < NACTV) { srcf = x; dsth = xh; }
    else { idx -= NACTV; srcf = enc; dsth = ench; }
    float4 v4 = ((const float4*)srcf)[idx];
    ((__half2*)dsth)[2 * idx]     = __floats2half2_rn(v4.x, v4.y);
    ((__half2*)dsth)[2 * idx + 1] = __floats2half2_rn(v4.z, v4.w);
}

// ---------------- fp16 tensor-core GEMM body (128x128 tile, BK=64) ----------
#define G16_SMEM (3 * 32768)

template <int K>
__device__ __forceinline__ void load_chunk(uint32_t sbase,
                                           const __half* __restrict__ A,
                                           const __half* __restrict__ Wt,
                                           int row0, int col0, int tid,
                                           int stage, int kt) {
    uint32_t sA = sbase + (uint32_t)stage * 32768u;
    uint32_t sB = sA + 16384u;
#pragma unroll
    for (int i = 0; i < 4; i++) {
        int li = tid + i * 256; int r = li >> 3, sg = li & 7;
        cp16(sA + sw_off(r, sg), A + (size_t)(row0 + r) * K + kt + sg * 8);
        cp16(sB + sw_off(r, sg), Wt + (size_t)(col0 + r) * K + kt + sg * 8);
    }
    asm volatile("cp.async.commit_group;");
}

template <int K>
__device__ __forceinline__ void gemm_body(const __half* __restrict__ A,
                                          const __half* __restrict__ Wt,
                                          const float* __restrict__ bias,
                                          const float* __restrict__ resid,
                                          float* __restrict__ Cf,
                                          __half* __restrict__ Ch,
                                          int M, int relu, int colt, int rowt,
                                          char* gsm)
{
    uint32_t sbase = smem_u32(gsm);
    int tid = threadIdx.x, lane = tid & 31, warp = tid >> 5;
    int wm = warp >> 2, wn = warp & 3;
    int gid = lane >> 2, tg = lane & 3;
    int j = lane >> 3, rr = lane & 7;
    int col0 = colt * 128, row0 = rowt * 128;

    float acc[4][4][4];
#pragma unroll
    for (int a = 0; a < 4; a++)
#pragma unroll
        for (int b = 0; b < 4; b++)
#pragma unroll
            for (int c = 0; c < 4; c++) acc[a][b][c] = 0.0f;

    constexpr int nch = K >> 6;
    load_chunk<K>(sbase, A, Wt, row0, col0, tid, 0, 0);
    load_chunk<K>(sbase, A, Wt, row0, col0, tid, 1, 64);

#pragma unroll 2
    for (int it = 0; it < nch; it++) {
        if (it + 1 < nch) asm volatile("cp.async.wait_group 1;");
        else              asm volatile("cp.async.wait_group 0;");
        __syncthreads();
        if (it + 2 < nch)
            load_chunk<K>(sbase, A, Wt, row0, col0, tid, (it + 2) % 3, (it + 2) * 64);
        uint32_t sA = sbase + (uint32_t)(it % 3) * 32768u;
        uint32_t sB = sA + 16384u;
#pragma unroll
        for (int ks = 0; ks < 4; ks++) {
            uint32_t a[4][4], bfr[2][4];
#pragma unroll
            for (int mt = 0; mt < 4; mt++)
                ldsm4(a[mt][0], a[mt][1], a[mt][2], a[mt][3],
                      sA + sw_off(wm * 64 + mt * 16 + (j & 1) * 8 + rr, ks * 2 + (j >> 1)));
#pragma unroll
            for (int p = 0; p < 2; p++)
                ldsm4(bfr[p][0], bfr[p][1], bfr[p][2], bfr[p][3],
                      sB + sw_off(wn * 32 + p * 16 + (j >> 1) * 8 + rr, ks * 2 + (j & 1)));
#pragma unroll
            for (int mt = 0; mt < 4; mt++)
#pragma unroll
                for (int nt = 0; nt < 4; nt++)
                    mma16816(acc[mt][nt], a[mt], &bfr[nt >> 1][(nt & 1) * 2]);
        }
    }

#pragma unroll
    for (int mt = 0; mt < 4; mt++)
#pragma unroll
        for (int nt = 0; nt < 4; nt++) {
            int r0 = row0 + wm * 64 + mt * 16 + gid;
            int c0 = col0 + wn * 32 + nt * 8 + tg * 2;
            float b0 = bias[c0], b1 = bias[c0 + 1];
            float v0 = acc[mt][nt][0] + b0, v1 = acc[mt][nt][1] + b1;
            float v2 = acc[mt][nt][2] + b0, v3 = acc[mt][nt][3] + b1;
            if (resid) {
                float2 ra = *(const float2*)(resid + (size_t)r0 * M + c0);
                float2 rb = *(const float2*)(resid + (size_t)(r0 + 8) * M + c0);
                v0 += ra.x; v1 += ra.y; v2 += rb.x; v3 += rb.y;
            }
            if (relu) {
                v0 = fmaxf(v0, 0.f); v1 = fmaxf(v1, 0.f);
                v2 = fmaxf(v2, 0.f); v3 = fmaxf(v3, 0.f);
            }
            if (Cf) {
                *(float2*)(Cf + (size_t)r0 * M + c0)       = make_float2(v0, v1);
                *(float2*)(Cf + (size_t)(r0 + 8) * M + c0) = make_float2(v2, v3);
            }
            if (Ch) {
                *(__half2*)(Ch + (size_t)r0 * M + c0)       = __floats2half2_rn(v0, v1);
                *(__half2*)(Ch + (size_t)(r0 + 8) * M + c0) = __floats2half2_rn(v2, v3);
            }
        }
}

template <int K>
__global__ void __launch_bounds__(256, 2)
gemm_std(const __half* __restrict__ A, const __half* __restrict__ Wt,
         const float* __restrict__ bias, const float* __restrict__ resid,
         float* __restrict__ Cf, __half* __restrict__ Ch, int M, int relu)
{
    extern __shared__ char gsm[];
    gemm_body<K>(A, Wt, bias, resid, Cf, Ch, M, relu, blockIdx.x, blockIdx.y, gsm);
}

// merged: two independent K=384 GEMMs in one launch (128-col tiles)
__global__ void __launch_bounds__(256, 2)
gemm_dual(const __half* __restrict__ A1, const __half* __restrict__ W1,
          const float* __restrict__ b1, __half* __restrict__ C1, int M1,
          const __half* __restrict__ A2, const __half* __restrict__ W2,
          const float* __restrict__ b2, __half* __restrict__ C2, int M2)
{
    extern __shared__ char gsm[];
    int t1 = M1 / 128;
    if ((int)blockIdx.x < t1)
        gemm_body<384>(A1, W1, b1, nullptr, nullptr, C1, M1, 0,
                       blockIdx.x, blockIdx.y, gsm);
    else
        gemm_body<384>(A2, W2, b2, nullptr, nullptr, C2, M2, 0,
                       blockIdx.x - t1, blockIdx.y, gsm);
}

// ---------------- big-tile GEMM: 256x128 CTA tile, 512 threads --------------
// For M=384 launches: grid (3, 64) = 192 CTAs = single wave.
#define GBIG_SMEM (3 * 49152)

template <int K>
__device__ __forceinline__ void load_chunk_big(uint32_t sbase,
                                               const __half* __restrict__ A,
                                               const __half* __restrict__ Wt,
                                               int row0, int col0, int tid,
                                               int stage, int kt) {
    uint32_t sA = sbase + (uint32_t)stage * 49152u;
    uint32_t sB = sA + 32768u;
#pragma unroll
    for (int i = 0; i < 4; i++) {            // A: 256 rows x 8 segs = 2048
        int li = tid + i * 512; int r = li >> 3, sg = li & 7;
        cp16(sA + sw_off(r, sg), A + (size_t)(row0 + r) * K + kt + sg * 8);
    }
#pragma unroll
    for (int i = 0; i < 2; i++) {            // B: 128 rows x 8 segs = 1024
        int li = tid + i * 512; int r = li >> 3, sg = li & 7;
        cp16(sB + sw_off(r, sg), Wt + (size_t)(col0 + r) * K + kt + sg * 8);
    }
    asm volatile("cp.async.commit_group;");
}

template <int K>
__global__ void __launch_bounds__(512, 1)
gemm_big(const __half* __restrict__ A, const __half* __restrict__ Wt,
         const float* __restrict__ bias, const float* __restrict__ resid,
         float* __restrict__ Cf, __half* __restrict__ Ch, int M, int relu)
{
    extern __shared__ char gsm[];
    uint32_t sbase = smem_u32(gsm);
    int tid = threadIdx.x, lane = tid & 31, warp = tid >> 5;
    int wm = warp >> 2, wn = warp & 3;       // 4 x 4 warp grid
    int gid = lane >> 2, tg = lane & 3;
    int j = lane >> 3, rr = lane & 7;
    int col0 = blockIdx.x * 128, row0 = blockIdx.y * 256;

    float acc[4][4][4];
#pragma unroll
    for (int a = 0; a < 4; a++)
#pragma unroll
        for (int b = 0; b < 4; b++)
#pragma unroll
            for (int c = 0; c < 4; c++) acc[a][b][c] = 0.0f;

    constexpr int nch = K >> 6;
    load_chunk_big<K>(sbase, A, Wt, row0, col0, tid, 0, 0);
    load_chunk_big<K>(sbase, A, Wt, row0, col0, tid, 1, 64);

#pragma unroll 2
    for (int it = 0; it < nch; it++) {
        if (it + 1 < nch) asm volatile("cp.async.wait_group 1;");
        else              asm volatile("cp.async.wait_group 0;");
        __syncthreads();
        if (it + 2 < nch)
            load_chunk_big<K>(sbase, A, Wt, row0, col0, tid, (it + 2) % 3, (it + 2) * 64);
        uint32_t sA = sbase + (uint32_t)(it % 3) * 49152u;
        uint32_t sB = sA + 32768u;
#pragma unroll
        for (int ks = 0; ks < 4; ks++) {
            uint32_t a[4][4], bfr[2][4];
#pragma unroll
            for (int mt = 0; mt < 4; mt++)
                ldsm4(a[mt][0], a[mt][1], a[mt][2], a[mt][3],
                      sA + sw_off(wm * 64 + mt * 16 + (j & 1) * 8 + rr, ks * 2 + (j >> 1)));
#pragma unroll
            for (int p = 0; p < 2; p++)
                ldsm4(bfr[p][0], bfr[p][1], bfr[p][2], bfr[p][3],
                      sB + sw_off(wn * 32 + p * 16 + (j >> 1) * 8 + rr, ks * 2 + (j & 1)));
#pragma unroll
            for (int mt = 0; mt < 4; mt++)
#pragma unroll
                for (int nt = 0; nt < 4; nt++)
                    mma16816(acc[mt][nt], a[mt], &bfr[nt >> 1][(nt & 1) * 2]);
        }
    }

#pragma unroll
    for (int mt = 0; mt < 4; mt++)
#pragma unroll
        for (int nt = 0; nt < 4; nt++) {
            int r0 = row0 + wm * 64 + mt * 16 + gid;
            int c0 = col0 + wn * 32 + nt * 8 + tg * 2;
            float b0 = bias[c0], b1 = bias[c0 + 1];
            float v0 = acc[mt][nt][0] + b0, v1 = acc[mt][nt][1] + b1;
            float v2 = acc[mt][nt][2] + b0, v3 = acc[mt][nt][3] + b1;
            if (resid) {
                float2 ra = *(const float2*)(resid + (size_t)r0 * M + c0);
                float2 rb = *(const float2*)(resid + (size_t)(r0 + 8) * M + c0);
                v0 += ra.x; v1 += ra.y; v2 += rb.x; v3 += rb.y;
            }
            if (relu) {
                v0 = fmaxf(v0, 0.f); v1 = fmaxf(v1, 0.f);
                v2 = fmaxf(v2, 0.f); v3 = fmaxf(v3, 0.f);
            }
            if (Cf) {
                *(float2*)(Cf + (size_t)r0 * M + c0)       = make_float2(v0, v1);
                *(float2*)(Cf + (size_t)(r0 + 8) * M + c0) = make_float2(v2, v3);
            }
            if (Ch) {
                *(__half2*)(Ch + (size_t)r0 * M + c0)       = __floats2half2_rn(v0, v1);
                *(__half2*)(Ch + (size_t)(r0 + 8) * M + c0) = __floats2half2_rn(v2, v3);
            }
        }
}

// ---------------- flash attention: 128 q-rows per CTA, 8 warps --------------
#define AT_SMEM (16384 + 2 * 16384)

__global__ void __launch_bounds__(256, 2)
attn16_kernel(const __half* __restrict__ Qg, int ldq,
              const __half* __restrict__ Kg, const __half* __restrict__ Vg, int ldkv,
              __half* __restrict__ Og)
{
    extern __shared__ __align__(128) char asmem[];
    uint32_t sbase = smem_u32(asmem);
    uint32_t sQ = sbase;
    int tid = threadIdx.x, lane = tid & 31, w = tid >> 5;
    int gid = lane >> 2, tg = lane & 3;
    int j = lane >> 3, rr = lane & 7;

    int bid = blockIdx.x;
    int qt = bid & 1, h = (bid >> 1) % HH, b = bid / (2 * HH);
    int t0 = qt * 128;
    int hoff = h * HSS;

    const __half* qrow = Qg + (size_t)(b * TT + t0) * ldq + hoff;
#pragma unroll
    for (int i = 0; i < 4; i++) {
        int li = tid + i * 256; int r = li >> 3, sg = li & 7;
        cp16(sQ + sw_off(r, sg), qrow + (size_t)r * ldq + sg * 8);
    }
#define KVLOAD(ut, bufi)                                                           \
    {                                                                              \
        uint32_t sK_ = sbase + 16384u + (uint32_t)(bufi) * 16384u;                 \
        uint32_t sV_ = sK_ + 8192u;                                                \
        const __half* kr = Kg + (size_t)(b * TT + (ut) * 64) * ldkv + hoff;        \
        const __half* vr = Vg + (size_t)(b * TT + (ut) * 64) * ldkv + hoff;        \
        _Pragma("unroll")                                                          \
        for (int i = 0; i < 2; i++) {                                              \
            int li = tid + i * 256; int r = li >> 3, sg = li & 7;                  \
            cp16(sK_ + sw_off(r, sg), kr + (size_t)r * ldkv + sg * 8);             \
            cp16(sV_ + sw_off(r, sg), vr + (size_t)r * ldkv + sg * 8);             \
        }                                                                          \
        asm volatile("cp.async.commit_group;");                                    \
    }
    KVLOAD(0, 0);
    asm volatile("cp.async.wait_group 0;");
    __syncthreads();

    uint32_t qf[4][4];
#pragma unroll
    for (int ks = 0; ks < 4; ks++)
        ldsm4(qf[ks][0], qf[ks][1], qf[ks][2], qf[ks][3],
              sQ + sw_off(w * 16 + (j & 1) * 8 + rr, ks * 2 + (j >> 1)));

    float o[8][4];
#pragma unroll
    for (int nt = 0; nt < 8; nt++)
#pragma unroll
        for (int e = 0; e < 4; e++) o[nt][e] = 0.0f;
    float m0 = -1e30f, m1 = -1e30f, l0 = 0.0f, l1 = 0.0f;

    int nkv = 2 * (qt + 1);
    int r0g = t0 + w * 16 + gid;
    for (int ut = 0; ut < nkv; ut++) {
        if (ut > 0) { asm volatile("cp.async.wait_group 0;"); __syncthreads(); }
        if (ut < nkv - 1) KVLOAD(ut + 1, (ut + 1) & 1);
        uint32_t sK = sbase + 16384u + (uint32_t)(ut & 1) * 16384u;
        uint32_t sV = sK + 8192u;

        float s[8][4];
#pragma unroll
        for (int nt = 0; nt < 8; nt++)
#pragma unroll
            for (int e = 0; e < 4; e++) s[nt][e] = 0.0f;
#pragma unroll
        for (int ks = 0; ks < 4; ks++) {
            uint32_t kb[4][4];
#pragma unroll
            for (int p = 0; p < 4; p++)
                ldsm4(kb[p][0], kb[p][1], kb[p][2], kb[p][3],
                      sK + sw_off(p * 16 + (j >> 1) * 8 + rr, ks * 2 + (j & 1)));
#pragma unroll
            for (int nt = 0; nt < 8; nt++)
                mma16816(s[nt], qf[ks], &kb[nt >> 1][(nt & 1) * 2]);
        }
        if (ut >= 2 * qt) {
#pragma unroll
            for (int nt = 0; nt < 8; nt++) {
                int u0 = ut * 64 + nt * 8 + tg * 2;
                if (u0     > r0g)     s[nt][0] = -1e30f;
                if (u0 + 1 > r0g)     s[nt][1] = -1e30f;
                if (u0     > r0g + 8) s[nt][2] = -1e30f;
                if (u0 + 1 > r0g + 8) s[nt][3] = -1e30f;
            }
        }
        float mx0 = -1e30f, mx1 = -1e30f;
#pragma unroll
        for (int nt = 0; nt < 8; nt++) {
            mx0 = fmaxf(mx0, fmaxf(s[nt][0], s[nt][1]));
            mx1 = fmaxf(mx1, fmaxf(s[nt][2], s[nt][3]));
        }
        mx0 = fmaxf(mx0, __shfl_xor_sync(~0u, mx0, 1));
        mx0 = fmaxf(mx0, __shfl_xor_sync(~0u, mx0, 2));
        mx1 = fmaxf(mx1, __shfl_xor_sync(~0u, mx1, 1));
        mx1 = fmaxf(mx1, __shfl_xor_sync(~0u, mx1, 2));
        float mn0 = fmaxf(m0, mx0), mn1 = fmaxf(m1, mx1);
        float f0 = __expf(m0 - mn0), f1 = __expf(m1 - mn1);
        m0 = mn0; m1 = mn1;
        float rs0 = 0.0f, rs1 = 0.0f;
#pragma unroll
        for (int nt = 0; nt < 8; nt++) {
            s[nt][0] = __expf(s[nt][0] - mn0); rs0 += s[nt][0];
            s[nt][1] = __expf(s[nt][1] - mn0); rs0 += s[nt][1];
            s[nt][2] = __expf(s[nt][2] - mn1); rs1 += s[nt][2];
            s[nt][3] = __expf(s[nt][3] - mn1); rs1 += s[nt][3];
        }
        rs0 += __shfl_xor_sync(~0u, rs0, 1); rs0 += __shfl_xor_sync(~0u, rs0, 2);
        rs1 += __shfl_xor_sync(~0u, rs1, 1); rs1 += __shfl_xor_sync(~0u, rs1, 2);
        l0 = l0 * f0 + rs0;
        l1 = l1 * f1 + rs1;
#pragma unroll
        for (int nt = 0; nt < 8; nt++) {
            o[nt][0] *= f0; o[nt][1] *= f0; o[nt][2] *= f1; o[nt][3] *= f1;
        }
        uint32_t pa[4][4];
#pragma unroll
        for (int kk = 0; kk < 4; kk++) {
            pa[kk][0] = ph2(s[2 * kk][0], s[2 * kk][1]);
            pa[kk][1] = ph2(s[2 * kk][2], s[2 * kk][3]);
            pa[kk][2] = ph2(s[2 * kk + 1][0], s[2 * kk + 1][1]);
            pa[kk][3] = ph2(s[2 * kk + 1][2], s[2 * kk + 1][3]);
        }
#pragma unroll
        for (int kk = 0; kk < 4; kk++) {
            uint32_t vb[4][4];
#pragma unroll
            for (int p = 0; p < 4; p++)
                ldsm4t(vb[p][0], vb[p][1], vb[p][2], vb[p][3],
                       sV + sw_off(kk * 16 + (j & 1) * 8 + rr, p * 2 + (j >> 1)));
#pragma unroll
            for (int nt = 0; nt < 8; nt++)
                mma16816(o[nt], pa[kk], &vb[nt >> 1][(nt & 1) * 2]);
        }
    }
    float i0 = 1.0f / l0, i1 = 1.0f / l1;
    __half* orow = Og + (size_t)(b * TT + t0) * EE + hoff;
#pragma unroll
    for (int nt = 0; nt < 8; nt++) {
        int c = nt * 8 + tg * 2;
        *(__half2*)(orow + (size_t)(w * 16 + gid) * EE + c) =
            __floats2half2_rn(o[nt][0] * i0, o[nt][1] * i0);
        *(__half2*)(orow + (size_t)(w * 16 + gid + 8) * EE + c) =
            __floats2half2_rn(o[nt][2] * i1, o[nt][3] * i1);
    }
}

// ---------------- LayerNorm: one warp per row, float4, shuffle-only ---------
__global__ void __launch_bounds__(256)
ln_kernel(const float* __restrict__ s_in,
          const float* __restrict__ g, const float* __restrict__ bt,
          float* __restrict__ o, __half* __restrict__ oh) {
    int warp = threadIdx.x >> 5, lane = threadIdx.x & 31;
    int row = blockIdx.x * 8 + warp;
    const float4* rp = (const float4*)(s_in + (size_t)row * EE);
    float4 v[3];
#pragma unroll
    for (int i = 0; i < 3; i++) v[i] = rp[lane + 32 * i];
    float s = 0.0f;
#pragma unroll
    for (int i = 0; i < 3; i++) s += v[i].x + v[i].y + v[i].z + v[i].w;
#pragma unroll
    for (int off = 16; off; off >>= 1) s += __shfl_xor_sync(~0u, s, off);
    float mean = s * (1.0f / EE);
    float sq = 0.0f;
#pragma unroll
    for (int i = 0; i < 3; i++) {
        float a0 = v[i].x - mean, a1 = v[i].y - mean;
        float a2 = v[i].z - mean, a3 = v[i].w - mean;
        sq += a0 * a0 + a1 * a1 + a2 * a2 + a3 * a3;
    }
#pragma unroll
    for (int off = 16; off; off >>= 1) sq += __shfl_xor_sync(~0u, sq, off);
    float inv = rsqrtf(sq * (1.0f / EE) + 1e-5f);
    float4* op = (float4*)(o + (size_t)row * EE);
    __half2* ohp = oh ? (__half2*)(oh + (size_t)row * EE) : nullptr;
#pragma unroll
    for (int i = 0; i < 3; i++) {
        int e4 = lane + 32 * i;
        float4 gg = *(const float4*)(g + e4 * 4);
        float4 bb = *(const float4*)(bt + e4 * 4);
        float4 r;
        r.x = (v[i].x - mean) * inv * gg.x + bb.x;
        r.y = (v[i].y - mean) * inv * gg.y + bb.y;
        r.z = (v[i].z - mean) * inv * gg.z + bb.z;
        r.w = (v[i].w - mean) * inv * gg.w + bb.w;
        op[e4] = r;
        if (ohp) {
            ohp[e4 * 2]     = __floats2half2_rn(r.x, r.y);
            ohp[e4 * 2 + 1] = __floats2half2_rn(r.z, r.w);
        }
    }
}

// ---------------- host orchestration ---------------------------------------
extern "C" void kernel_launch(void* const* d_in, const int* in_sizes, int n_in,
                              void* d_out, int out_size) {
    const float* enc = (const float*)d_in[0];
    const float* x   = (const float*)d_in[1];
    const float* sa1_wq = (const float*)d_in[2];
    const float* sa1_bq = (const float*)d_in[3];
    const float* sa1_wk = (const float*)d_in[4];
    const float* sa1_bk = (const float*)d_in[5];
    const float* sa1_wv = (const float*)d_in[6];
    const float* sa1_bv = (const float*)d_in[7];
    const float* sa1_pw = (const float*)d_in[8];
    const float* sa1_pb = (const float*)d_in[9];
    const float* sa2_wq = (const float*)d_in[10];
    const float* sa2_bq = (const float*)d_in[11];
    const float* sa2_wk = (const float*)d_in[12];
    const float* sa2_bk = (const float*)d_in[13];
    const float* sa2_wv = (const float*)d_in[14];
    const float* sa2_bv = (const float*)d_in[15];
    const float* sa2_pw = (const float*)d_in[16];
    const float* sa2_pb = (const float*)d_in[17];
    const float* ff_w1  = (const float*)d_in[18];
    const float* ff_b1  = (const float*)d_in[19];
    const float* ff_w2  = (const float*)d_in[20];
    const float* ff_b2  = (const float*)d_in[21];
    const float* ln1_g  = (const float*)d_in[22];
    const float* ln1_b  = (const float*)d_in[23];
    const float* ln2_g  = (const float*)d_in[24];
    const float* ln2_b  = (const float*)d_in[25];
    const float* ln3_g  = (const float*)d_in[26];
    const float* ln3_b  = (const float*)d_in[27];
    float* out = (float*)d_out;

    cudaFuncSetAttribute(gemm_std<384>,
                         cudaFuncAttributeMaxDynamicSharedMemorySize, G16_SMEM);
    cudaFuncSetAttribute(gemm_dual,
                         cudaFuncAttributeMaxDynamicSharedMemorySize, G16_SMEM);
    cudaFuncSetAttribute(gemm_big<384>,
                         cudaFuncAttributeMaxDynamicSharedMemorySize, GBIG_SMEM);
    cudaFuncSetAttribute(gemm_big<1536>,
                         cudaFuncAttributeMaxDynamicSharedMemorySize, GBIG_SMEM);
    cudaFuncSetAttribute(attn16_kernel,
                         cudaFuncAttributeMaxDynamicSharedMemorySize, AT_SMEM);

    __half *pqkv, *pkv, *pq, *patt, *phid, *pxh, *pench, *po1h, *po2h;
    __half *pwqkv, *pwq2, *pwkv, *pwp1, *pwp2, *pwf1, *pwf2;
    float *pbuf, *po1, *po2, *pbqkv, *pbkv, *pbq2;
    cudaGetSymbolAddress((void**)&pqkv,  g_qkv_h);
    cudaGetSymbolAddress((void**)&pkv,   g_kv_h);
    cudaGetSymbolAddress((void**)&pq,    g_q_h);
    cudaGetSymbolAddress((void**)&patt,  g_att_h);
    cudaGetSymbolAddress((void**)&phid,  g_hid_h);
    cudaGetSymbolAddress((void**)&pxh,   g_xh);
    cudaGetSymbolAddress((void**)&pench, g_ench);
    cudaGetSymbolAddress((void**)&po1h,  g_po1h);
    cudaGetSymbolAddress((void**)&po2h,  g_po2h);
    cudaGetSymbolAddress((void**)&pbuf,  g_buf);
    cudaGetSymbolAddress((void**)&po1,   g_o1);
    cudaGetSymbolAddress((void**)&po2,   g_o2);
    cudaGetSymbolAddress((void**)&pwqkv, g_wqkvh);
    cudaGetSymbolAddress((void**)&pwq2,  g_wq2h);
    cudaGetSymbolAddress((void**)&pwkv,  g_wkvh);
    cudaGetSymbolAddress((void**)&pwp1,  g_wp1h);
    cudaGetSymbolAddress((void**)&pwp2,  g_wp2h);
    cudaGetSymbolAddress((void**)&pwf1,  g_wf1h);
    cudaGetSymbolAddress((void**)&pwf2,  g_wf2h);
    cudaGetSymbolAddress((void**)&pbqkv, g_bqkv);
    cudaGetSymbolAddress((void**)&pbkv,  g_bkv);
    cudaGetSymbolAddress((void**)&pbq2,  g_bq2);

    megapack_kernel<<<(int)((PACK_TOTAL + 255) / 256), 256>>>(
        sa1_wq, sa1_wk, sa1_wv, sa2_wq, sa2_wk, sa2_wv,
        sa1_pw, sa2_pw, ff_w1, ff_w2,
        sa1_bq, sa1_bk, sa1_bv, sa2_bq, sa2_bk, sa2_bv,
        x, enc,
        pwqkv, pwq2, pwkv, pwp1, pwp2, pwf1, pwf2,
        pbqkv, pbkv, pbq2, pxh, pench);

    // ---- fused: QKV(x) + KV(enc) in one launch (both depend only on pack) --
    gemm_dual<<<dim3(15, 128), 256, G16_SMEM>>>(
        pxh, pwqkv, pbqkv, pqkv, 3 * EE,
        pench, pwkv, pbkv, pkv, 2 * EE);

    // ---- block 1: masked self-attention + add&norm ----
    attn16_kernel<<<BB * HH * 2, 256, AT_SMEM>>>(pqkv, 3 * EE,
                                                 pqkv + EE, pqkv + 2 * EE, 3 * EE, patt);
    gemm_big<384><<<dim3(3, 64), 512, GBIG_SMEM>>>(
        patt, pwp1, sa1_pb, x, pbuf, nullptr, EE, 0);           // pbuf = x + proj
    ln_kernel<<<NROWS / 8, 256>>>(pbuf, ln1_g, ln1_b, po1, po1h);

    // ---- block 2: cross-attention (still causal-masked) + add&norm ----
    gemm_big<384><<<dim3(3, 64), 512, GBIG_SMEM>>>(
        po1h, pwq2, pbq2, nullptr, nullptr, pq, EE, 0);
    attn16_kernel<<<BB * HH * 2, 256, AT_SMEM>>>(pq, EE,
                                                 pkv, pkv + EE, 2 * EE, patt);
    gemm_big<384><<<dim3(3, 64), 512, GBIG_SMEM>>>(
        patt, pwp2, sa2_pb, po1, pbuf, nullptr, EE, 0);         // pbuf = o1 + proj
    ln_kernel<<<NROWS / 8, 256>>>(pbuf, ln2_g, ln2_b, po2, po2h);

    // ---- FFN + add&norm ----
    gemm_std<384><<<dim3(12, 128), 256, G16_SMEM>>>(
        po2h, pwf1, ff_b1, nullptr, nullptr, phid, FFD, 1);
    gemm_big<1536><<<dim3(3, 64), 512, GBIG_SMEM>>>(
        phid, pwf2, ff_b2, po2, pbuf, nullptr, EE, 0);          // pbuf = o2 + ff
    ln_kernel<<<NROWS / 8, 256>>>(pbuf, ln3_g, ln3_b, out, nullptr);
}

// round 11
// speedup vs baseline: 1.1267x; 1.1267x over previous
#include <cuda_runtime.h>
#include <cuda_fp16.h>
#include <cstdint>
#include <cstddef>

// Problem constants
#define EE   384
#define HH   6
#define HSS  64
#define BB   64
#define TT   256
#define FFD  1536
#define NROWS (BB*TT)          // 16384

// ---------------- scratch (device globals; no allocation allowed) ----------
__device__ __half g_qkv_h[(size_t)NROWS * 3 * EE];
__device__ __half g_kv_h[(size_t)NROWS * 2 * EE];
__device__ __half g_q_h[(size_t)NROWS * EE];
__device__ __half g_att_h[(size_t)NROWS * EE];
__device__ __half g_hid_h[(size_t)NROWS * FFD];
__device__ __half g_xh[(size_t)NROWS * EE];
__device__ __half g_ench[(size_t)NROWS * EE];
__device__ __half g_po1h[(size_t)NROWS * EE];
__device__ __half g_po2h[(size_t)NROWS * EE];
__device__ float  g_buf[(size_t)NROWS * EE];
__device__ float  g_o1[(size_t)NROWS * EE];
__device__ float  g_o2[(size_t)NROWS * EE];
// fp16 weights, transposed to [out][in]
__device__ __half g_wqkvh[3 * EE * EE];
__device__ __half g_wq2h[EE * EE];
__device__ __half g_wkvh[2 * EE * EE];
__device__ __half g_wp1h[EE * EE];
__device__ __half g_wp2h[EE * EE];
__device__ __half g_wf1h[FFD * EE];
__device__ __half g_wf2h[EE * FFD];
__device__ float  g_bqkv[3 * EE];
__device__ float  g_bkv[2 * EE];
__device__ float  g_bq2[EE];

// ---------------- PTX helpers ----------------------------------------------
__device__ __forceinline__ uint32_t smem_u32(const void* p) {
    uint32_t a;
    asm("{ .reg .u64 t; cvta.to.shared.u64 t, %1; cvt.u32.u64 %0, t; }" : "=r"(a) : "l"(p));
    return a;
}
__device__ __forceinline__ void cp16(uint32_t dst, const void* src) {
    asm volatile("cp.async.cg.shared.global [%0], [%1], 16;" :: "r"(dst), "l"(src));
}
__device__ __forceinline__ void ldsm4(uint32_t& r0, uint32_t& r1, uint32_t& r2, uint32_t& r3,
                                      uint32_t addr) {
    asm volatile("ldmatrix.sync.aligned.m8n8.x4.shared.b16 {%0,%1,%2,%3}, [%4];"
                 : "=r"(r0), "=r"(r1), "=r"(r2), "=r"(r3) : "r"(addr));
}
__device__ __forceinline__ void ldsm4t(uint32_t& r0, uint32_t& r1, uint32_t& r2, uint32_t& r3,
                                       uint32_t addr) {
    asm volatile("ldmatrix.sync.aligned.m8n8.x4.trans.shared.b16 {%0,%1,%2,%3}, [%4];"
                 : "=r"(r0), "=r"(r1), "=r"(r2), "=r"(r3) : "r"(addr));
}
__device__ __forceinline__ void mma16816(float* c, const uint32_t* a, const uint32_t* b) {
    asm volatile(
        "mma.sync.aligned.m16n8k16.row.col.f32.f16.f16.f32 "
        "{%0,%1,%2,%3}, {%4,%5,%6,%7}, {%8,%9}, {%0,%1,%2,%3};"
        : "+f"(c[0]), "+f"(c[1]), "+f"(c[2]), "+f"(c[3])
        : "r"(a[0]), "r"(a[1]), "r"(a[2]), "r"(a[3]), "r"(b[0]), "r"(b[1]));
}
__device__ __forceinline__ uint32_t ph2(float a, float b) {
    __half2 h = __floats2half2_rn(a, b);
    return *reinterpret_cast<uint32_t*>(&h);
}
__device__ __forceinline__ uint32_t sw_off(int r, int seg) {
    return (uint32_t)(r * 128 + (((seg ^ (r & 7)) & 7) << 4));
}

// ---------------- megapack --------------------------------------------------
#define HPK 147456
#define S_ATTNW (6*HPK)
#define S_PROJ  (2*HPK)
#define S_FF    (EE*FFD)
#define NACT    ((size_t)NROWS*EE)
#define NACTV   ((long long)(NACT/4))
#define PACK_TOTAL ((long long)S_ATTNW + S_PROJ + 2*S_FF + 3*EE + 2*EE + EE + 2*NACTV)

__global__ void megapack_kernel(
    const float* __restrict__ wq1, const float* __restrict__ wk1, const float* __restrict__ wv1,
    const float* __restrict__ wq2, const float* __restrict__ wk2, const float* __restrict__ wv2,
    const float* __restrict__ pw1, const float* __restrict__ pw2,
    const float* __restrict__ fw1, const float* __restrict__ fw2,
    const float* __restrict__ bq1, const float* __restrict__ bk1, const float* __restrict__ bv1,
    const float* __restrict__ bq2, const float* __restrict__ bk2, const float* __restrict__ bv2,
    const float* __restrict__ x, const float* __restrict__ enc,
    __half* __restrict__ wqkv, __half* __restrict__ wqo, __half* __restrict__ wkv,
    __half* __restrict__ wp1o, __half* __restrict__ wp2o,
    __half* __restrict__ wf1o, __half* __restrict__ wf2o,
    float* __restrict__ bqkv, float* __restrict__ bkv, float* __restrict__ bq2o,
    __half* __restrict__ xh, __half* __restrict__ ench)
{
    long long idx = (long long)blockIdx.x * 256 + threadIdx.x;
    if (idx >= PACK_TOTAL) return;
    const float scale = rsqrtf((float)EE);
    if (idx < S_ATTNW) {
        int reg = (int)(idx / HPK), i = (int)(idx % HPK);
        int h = i / (EE * HSS), e = (i / HSS) % EE, s = i % HSS;
        int out = h * HSS + s;
        float v; __half* dst; int rowoff;
        switch (reg) {
            case 0: v = wq1[i] * scale; dst = wqkv; rowoff = 0;      break;
            case 1: v = wk1[i];         dst = wqkv; rowoff = EE;     break;
            case 2: v = wv1[i];         dst = wqkv; rowoff = 2 * EE; break;
            case 3: v = wq2[i] * scale; dst = wqo;  rowoff = 0;      break;
            case 4: v = wk2[i];         dst = wkv;  rowoff = 0;      break;
            default: v = wv2[i];        dst = wkv;  rowoff = EE;     break;
        }
        dst[(size_t)(rowoff + out) * EE + e] = __float2half_rn(v);
        return;
    }
    idx -= S_ATTNW;
    if (idx < S_PROJ) {
        int reg = (int)(idx / HPK), i = (int)(idx % HPK);
        int e = i / EE, o = i % EE;
        (reg ? wp2o : wp1o)[(size_t)o * EE + e] = __float2half_rn((reg ? pw2 : pw1)[i]);
        return;
    }
    idx -= S_PROJ;
    if (idx < S_FF) {
        int e = (int)(idx / FFD), o = (int)(idx % FFD);
        wf1o[(size_t)o * EE + e] = __float2half_rn(fw1[idx]);
        return;
    }
    idx -= S_FF;
    if (idx < S_FF) {
        int e = (int)(idx / EE), o = (int)(idx % EE);
        wf2o[(size_t)o * FFD + e] = __float2half_rn(fw2[idx]);
        return;
    }
    idx -= S_FF;
    if (idx < 3 * EE) {
        int sub = (int)(idx / EE), jj = (int)(idx % EE);
        bqkv[idx] = sub == 0 ? bq1[jj] * scale : sub == 1 ? bk1[jj] : bv1[jj];
        return;
    }
    idx -= 3 * EE;
    if (idx < 2 * EE) { bkv[idx] = idx < EE ? bk2[idx] : bv2[idx - EE]; return; }
    idx -= 2 * EE;
    if (idx < EE) { bq2o[idx] = bq2[idx] * scale; return; }
    idx -= EE;
    const float* srcf; __half* dsth;
    if (idx < NACTV) { srcf = x; dsth = xh; }
    else { idx -= NACTV; srcf = enc; dsth = ench; }
    float4 v4 = ((const float4*)srcf)[idx];
    ((__half2*)dsth)[2 * idx]     = __floats2half2_rn(v4.x, v4.y);
    ((__half2*)dsth)[2 * idx + 1] = __floats2half2_rn(v4.z, v4.w);
}

// ---------------- fp16 tensor-core GEMM body (128x128 tile, BK=64) ----------
#define G16_SMEM (3 * 32768)

template <int K>
__device__ __forceinline__ void load_chunk(uint32_t sbase,
                                           const __half* __restrict__ A,
                                           const __half* __restrict__ Wt,
                                           int row0, int col0, int tid,
                                           int stage, int kt) {
    uint32_t sA = sbase + (uint32_t)stage * 32768u;
    uint32_t sB = sA + 16384u;
#pragma unroll
    for (int i = 0; i < 4; i++) {
        int li = tid + i * 256; int r = li >> 3, sg = li & 7;
        cp16(sA + sw_off(r, sg), A + (size_t)(row0 + r) * K + kt + sg * 8);
        cp16(sB + sw_off(r, sg), Wt + (size_t)(col0 + r) * K + kt + sg * 8);
    }
    asm volatile("cp.async.commit_group;");
}

template <int K>
__device__ __forceinline__ void gemm_body(const __half* __restrict__ A,
                                          const __half* __restrict__ Wt,
                                          const float* __restrict__ bias,
                                          const float* __restrict__ resid,
                                          float* __restrict__ Cf,
                                          __half* __restrict__ Ch,
                                          int M, int relu, int colt, int rowt,
                                          char* gsm)
{
    uint32_t sbase = smem_u32(gsm);
    int tid = threadIdx.x, lane = tid & 31, warp = tid >> 5;
    int wm = warp >> 2, wn = warp & 3;
    int gid = lane >> 2, tg = lane & 3;
    int j = lane >> 3, rr = lane & 7;
    int col0 = colt * 128, row0 = rowt * 128;

    float acc[4][4][4];
#pragma unroll
    for (int a = 0; a < 4; a++)
#pragma unroll
        for (int b = 0; b < 4; b++)
#pragma unroll
            for (int c = 0; c < 4; c++) acc[a][b][c] = 0.0f;

    constexpr int nch = K >> 6;
    load_chunk<K>(sbase, A, Wt, row0, col0, tid, 0, 0);
    load_chunk<K>(sbase, A, Wt, row0, col0, tid, 1, 64);

#pragma unroll 2
    for (int it = 0; it < nch; it++) {
        if (it + 1 < nch) asm volatile("cp.async.wait_group 1;");
        else              asm volatile("cp.async.wait_group 0;");
        __syncthreads();
        if (it + 2 < nch)
            load_chunk<K>(sbase, A, Wt, row0, col0, tid, (it + 2) % 3, (it + 2) * 64);
        uint32_t sA = sbase + (uint32_t)(it % 3) * 32768u;
        uint32_t sB = sA + 16384u;
#pragma unroll
        for (int ks = 0; ks < 4; ks++) {
            uint32_t a[4][4], bfr[2][4];
#pragma unroll
            for (int mt = 0; mt < 4; mt++)
                ldsm4(a[mt][0], a[mt][1], a[mt][2], a[mt][3],
                      sA + sw_off(wm * 64 + mt * 16 + (j & 1) * 8 + rr, ks * 2 + (j >> 1)));
#pragma unroll
            for (int p = 0; p < 2; p++)
                ldsm4(bfr[p][0], bfr[p][1], bfr[p][2], bfr[p][3],
                      sB + sw_off(wn * 32 + p * 16 + (j >> 1) * 8 + rr, ks * 2 + (j & 1)));
#pragma unroll
            for (int mt = 0; mt < 4; mt++)
#pragma unroll
                for (int nt = 0; nt < 4; nt++)
                    mma16816(acc[mt][nt], a[mt], &bfr[nt >> 1][(nt & 1) * 2]);
        }
    }

#pragma unroll
    for (int mt = 0; mt < 4; mt++)
#pragma unroll
        for (int nt = 0; nt < 4; nt++) {
            int r0 = row0 + wm * 64 + mt * 16 + gid;
            int c0 = col0 + wn * 32 + nt * 8 + tg * 2;
            float b0 = bias[c0], b1 = bias[c0 + 1];
            float v0 = acc[mt][nt][0] + b0, v1 = acc[mt][nt][1] + b1;
            float v2 = acc[mt][nt][2] + b0, v3 = acc[mt][nt][3] + b1;
            if (resid) {
                float2 ra = *(const float2*)(resid + (size_t)r0 * M + c0);
                float2 rb = *(const float2*)(resid + (size_t)(r0 + 8) * M + c0);
                v0 += ra.x; v1 += ra.y; v2 += rb.x; v3 += rb.y;
            }
            if (relu) {
                v0 = fmaxf(v0, 0.f); v1 = fmaxf(v1, 0.f);
                v2 = fmaxf(v2, 0.f); v3 = fmaxf(v3, 0.f);
            }
            if (Cf) {
                *(float2*)(Cf + (size_t)r0 * M + c0)       = make_float2(v0, v1);
                *(float2*)(Cf + (size_t)(r0 + 8) * M + c0) = make_float2(v2, v3);
            }
            if (Ch) {
                *(__half2*)(Ch + (size_t)r0 * M + c0)       = __floats2half2_rn(v0, v1);
                *(__half2*)(Ch + (size_t)(r0 + 8) * M + c0) = __floats2half2_rn(v2, v3);
            }
        }
}

template <int K>
__global__ void __launch_bounds__(256, 2)
gemm_std(const __half* __restrict__ A, const __half* __restrict__ Wt,
         const float* __restrict__ bias, const float* __restrict__ resid,
         float* __restrict__ Cf, __half* __restrict__ Ch, int M, int relu)
{
    extern __shared__ char gsm[];
    gemm_body<K>(A, Wt, bias, resid, Cf, Ch, M, relu, blockIdx.x, blockIdx.y, gsm);
}

// merged: two independent K=384 GEMMs in one launch (128-col tiles)
__global__ void __launch_bounds__(256, 2)
gemm_dual(const __half* __restrict__ A1, const __half* __restrict__ W1,
          const float* __restrict__ b1, __half* __restrict__ C1, int M1,
          const __half* __restrict__ A2, const __half* __restrict__ W2,
          const float* __restrict__ b2, __half* __restrict__ C2, int M2)
{
    extern __shared__ char gsm[];
    int t1 = M1 / 128;
    if ((int)blockIdx.x < t1)
        gemm_body<384>(A1, W1, b1, nullptr, nullptr, C1, M1, 0,
                       blockIdx.x, blockIdx.y, gsm);
    else
        gemm_body<384>(A2, W2, b2, nullptr, nullptr, C2, M2, 0,
                       blockIdx.x - t1, blockIdx.y, gsm);
}

// ---------------- flash attention: 128 q-rows per CTA, 8 warps --------------
#define AT_SMEM (16384 + 2 * 16384)

__global__ void __launch_bounds__(256, 2)
attn16_kernel(const __half* __restrict__ Qg, int ldq,
              const __half* __restrict__ Kg, const __half* __restrict__ Vg, int ldkv,
              __half* __restrict__ Og)
{
    extern __shared__ __align__(128) char asmem[];
    uint32_t sbase = smem_u32(asmem);
    uint32_t sQ = sbase;
    int tid = threadIdx.x, lane = tid & 31, w = tid >> 5;
    int gid = lane >> 2, tg = lane & 3;
    int j = lane >> 3, rr = lane & 7;

    int bid = blockIdx.x;
    int qt = bid & 1, h = (bid >> 1) % HH, b = bid / (2 * HH);
    int t0 = qt * 128;
    int hoff = h * HSS;

    const __half* qrow = Qg + (size_t)(b * TT + t0) * ldq + hoff;
#pragma unroll
    for (int i = 0; i < 4; i++) {
        int li = tid + i * 256; int r = li >> 3, sg = li & 7;
        cp16(sQ + sw_off(r, sg), qrow + (size_t)r * ldq + sg * 8);
    }
#define KVLOAD(ut, bufi)                                                           \
    {                                                                              \
        uint32_t sK_ = sbase + 16384u + (uint32_t)(bufi) * 16384u;                 \
        uint32_t sV_ = sK_ + 8192u;                                                \
        const __half* kr = Kg + (size_t)(b * TT + (ut) * 64) * ldkv + hoff;        \
        const __half* vr = Vg + (size_t)(b * TT + (ut) * 64) * ldkv + hoff;        \
        _Pragma("unroll")                                                          \
        for (int i = 0; i < 2; i++) {                                              \
            int li = tid + i * 256; int r = li >> 3, sg = li & 7;                  \
            cp16(sK_ + sw_off(r, sg), kr + (size_t)r * ldkv + sg * 8);             \
            cp16(sV_ + sw_off(r, sg), vr + (size_t)r * ldkv + sg * 8);             \
        }                                                                          \
        asm volatile("cp.async.commit_group;");                                    \
    }
    KVLOAD(0, 0);
    asm volatile("cp.async.wait_group 0;");
    __syncthreads();

    uint32_t qf[4][4];
#pragma unroll
    for (int ks = 0; ks < 4; ks++)
        ldsm4(qf[ks][0], qf[ks][1], qf[ks][2], qf[ks][3],
              sQ + sw_off(w * 16 + (j & 1) * 8 + rr, ks * 2 + (j >> 1)));

    float o[8][4];
#pragma unroll
    for (int nt = 0; nt < 8; nt++)
#pragma unroll
        for (int e = 0; e < 4; e++) o[nt][e] = 0.0f;
    float m0 = -1e30f, m1 = -1e30f, l0 = 0.0f, l1 = 0.0f;

    int nkv = 2 * (qt + 1);
    int r0g = t0 + w * 16 + gid;
    for (int ut = 0; ut < nkv; ut++) {
        if (ut > 0) { asm volatile("cp.async.wait_group 0;"); __syncthreads(); }
        if (ut < nkv - 1) KVLOAD(ut + 1, (ut + 1) & 1);
        uint32_t sK = sbase + 16384u + (uint32_t)(ut & 1) * 16384u;
        uint32_t sV = sK + 8192u;

        float s[8][4];
#pragma unroll
        for (int nt = 0; nt < 8; nt++)
#pragma unroll
            for (int e = 0; e < 4; e++) s[nt][e] = 0.0f;
#pragma unroll
        for (int ks = 0; ks < 4; ks++) {
            uint32_t kb[4][4];
#pragma unroll
            for (int p = 0; p < 4; p++)
                ldsm4(kb[p][0], kb[p][1], kb[p][2], kb[p][3],
                      sK + sw_off(p * 16 + (j >> 1) * 8 + rr, ks * 2 + (j & 1)));
#pragma unroll
            for (int nt = 0; nt < 8; nt++)
                mma16816(s[nt], qf[ks], &kb[nt >> 1][(nt & 1) * 2]);
        }
        if (ut >= 2 * qt) {
#pragma unroll
            for (int nt = 0; nt < 8; nt++) {
                int u0 = ut * 64 + nt * 8 + tg * 2;
                if (u0     > r0g)     s[nt][0] = -1e30f;
                if (u0 + 1 > r0g)     s[nt][1] = -1e30f;
                if (u0     > r0g + 8) s[nt][2] = -1e30f;
                if (u0 + 1 > r0g + 8) s[nt][3] = -1e30f;
            }
        }
        float mx0 = -1e30f, mx1 = -1e30f;
#pragma unroll
        for (int nt = 0; nt < 8; nt++) {
            mx0 = fmaxf(mx0, fmaxf(s[nt][0], s[nt][1]));
            mx1 = fmaxf(mx1, fmaxf(s[nt][2], s[nt][3]));
        }
        mx0 = fmaxf(mx0, __shfl_xor_sync(~0u, mx0, 1));
        mx0 = fmaxf(mx0, __shfl_xor_sync(~0u, mx0, 2));
        mx1 = fmaxf(mx1, __shfl_xor_sync(~0u, mx1, 1));
        mx1 = fmaxf(mx1, __shfl_xor_sync(~0u, mx1, 2));
        float mn0 = fmaxf(m0, mx0), mn1 = fmaxf(m1, mx1);
        float f0 = __expf(m0 - mn0), f1 = __expf(m1 - mn1);
        m0 = mn0; m1 = mn1;
        float rs0 = 0.0f, rs1 = 0.0f;
#pragma unroll
        for (int nt = 0; nt < 8; nt++) {
            s[nt][0] = __expf(s[nt][0] - mn0); rs0 += s[nt][0];
            s[nt][1] = __expf(s[nt][1] - mn0); rs0 += s[nt][1];
            s[nt][2] = __expf(s[nt][2] - mn1); rs1 += s[nt][2];
            s[nt][3] = __expf(s[nt][3] - mn1); rs1 += s[nt][3];
        }
        rs0 += __shfl_xor_sync(~0u, rs0, 1); rs0 += __shfl_xor_sync(~0u, rs0, 2);
        rs1 += __shfl_xor_sync(~0u, rs1, 1); rs1 += __shfl_xor_sync(~0u, rs1, 2);
        l0 = l0 * f0 + rs0;
        l1 = l1 * f1 + rs1;
#pragma unroll
        for (int nt = 0; nt < 8; nt++) {
            o[nt][0] *= f0; o[nt][1] *= f0; o[nt][2] *= f1; o[nt][3] *= f1;
        }
        uint32_t pa[4][4];
#pragma unroll
        for (int kk = 0; kk < 4; kk++) {
            pa[kk][0] = ph2(s[2 * kk][0], s[2 * kk][1]);
            pa[kk][1] = ph2(s[2 * kk][2], s[2 * kk][3]);
            pa[kk][2] = ph2(s[2 * kk + 1][0], s[2 * kk + 1][1]);
            pa[kk][3] = ph2(s[2 * kk + 1][2], s[2 * kk + 1][3]);
        }
#pragma unroll
        for (int kk = 0; kk < 4; kk++) {
            uint32_t vb[4][4];
#pragma unroll
            for (int p = 0; p < 4; p++)
                ldsm4t(vb[p][0], vb[p][1], vb[p][2], vb[p][3],
                       sV + sw_off(kk * 16 + (j & 1) * 8 + rr, p * 2 + (j >> 1)));
#pragma unroll
            for (int nt = 0; nt < 8; nt++)
                mma16816(o[nt], pa[kk], &vb[nt >> 1][(nt & 1) * 2]);
        }
    }
    float i0 = 1.0f / l0, i1 = 1.0f / l1;
    __half* orow = Og + (size_t)(b * TT + t0) * EE + hoff;
#pragma unroll
    for (int nt = 0; nt < 8; nt++) {
        int c = nt * 8 + tg * 2;
        *(__half2*)(orow + (size_t)(w * 16 + gid) * EE + c) =
            __floats2half2_rn(o[nt][0] * i0, o[nt][1] * i0);
        *(__half2*)(orow + (size_t)(w * 16 + gid + 8) * EE + c) =
            __floats2half2_rn(o[nt][2] * i1, o[nt][3] * i1);
    }
}

// ---------------- LayerNorm: one warp per row, float4, shuffle-only ---------
__global__ void __launch_bounds__(256)
ln_kernel(const float* __restrict__ s_in,
          const float* __restrict__ g, const float* __restrict__ bt,
          float* __restrict__ o, __half* __restrict__ oh) {
    int warp = threadIdx.x >> 5, lane = threadIdx.x & 31;
    int row = blockIdx.x * 8 + warp;
    const float4* rp = (const float4*)(s_in + (size_t)row * EE);
    float4 v[3];
#pragma unroll
    for (int i = 0; i < 3; i++) v[i] = rp[lane + 32 * i];
    float s = 0.0f;
#pragma unroll
    for (int i = 0; i < 3; i++) s += v[i].x + v[i].y + v[i].z + v[i].w;
#pragma unroll
    for (int off = 16; off; off >>= 1) s += __shfl_xor_sync(~0u, s, off);
    float mean = s * (1.0f / EE);
    float sq = 0.0f;
#pragma unroll
    for (int i = 0; i < 3; i++) {
        float a0 = v[i].x - mean, a1 = v[i].y - mean;
        float a2 = v[i].z - mean, a3 = v[i].w - mean;
        sq += a0 * a0 + a1 * a1 + a2 * a2 + a3 * a3;
    }
#pragma unroll
    for (int off = 16; off; off >>= 1) sq += __shfl_xor_sync(~0u, sq, off);
    float inv = rsqrtf(sq * (1.0f / EE) + 1e-5f);
    float4* op = (float4*)(o + (size_t)row * EE);
    __half2* ohp = oh ? (__half2*)(oh + (size_t)row * EE) : nullptr;
#pragma unroll
    for (int i = 0; i < 3; i++) {
        int e4 = lane + 32 * i;
        float4 gg = *(const float4*)(g + e4 * 4);
        float4 bb = *(const float4*)(bt + e4 * 4);
        float4 r;
        r.x = (v[i].x - mean) * inv * gg.x + bb.x;
        r.y = (v[i].y - mean) * inv * gg.y + bb.y;
        r.z = (v[i].z - mean) * inv * gg.z + bb.z;
        r.w = (v[i].w - mean) * inv * gg.w + bb.w;
        op[e4] = r;
        if (ohp) {
            ohp[e4 * 2]     = __floats2half2_rn(r.x, r.y);
            ohp[e4 * 2 + 1] = __floats2half2_rn(r.z, r.w);
        }
    }
}

// ---------------- host orchestration ---------------------------------------
extern "C" void kernel_launch(void* const* d_in, const int* in_sizes, int n_in,
                              void* d_out, int out_size) {
    const float* enc = (const float*)d_in[0];
    const float* x   = (const float*)d_in[1];
    const float* sa1_wq = (const float*)d_in[2];
    const float* sa1_bq = (const float*)d_in[3];
    const float* sa1_wk = (const float*)d_in[4];
    const float* sa1_bk = (const float*)d_in[5];
    const float* sa1_wv = (const float*)d_in[6];
    const float* sa1_bv = (const float*)d_in[7];
    const float* sa1_pw = (const float*)d_in[8];
    const float* sa1_pb = (const float*)d_in[9];
    const float* sa2_wq = (const float*)d_in[10];
    const float* sa2_bq = (const float*)d_in[11];
    const float* sa2_wk = (const float*)d_in[12];
    const float* sa2_bk = (const float*)d_in[13];
    const float* sa2_wv = (const float*)d_in[14];
    const float* sa2_bv = (const float*)d_in[15];
    const float* sa2_pw = (const float*)d_in[16];
    const float* sa2_pb = (const float*)d_in[17];
    const float* ff_w1  = (const float*)d_in[18];
    const float* ff_b1  = (const float*)d_in[19];
    const float* ff_w2  = (const float*)d_in[20];
    const float* ff_b2  = (const float*)d_in[21];
    const float* ln1_g  = (const float*)d_in[22];
    const float* ln1_b  = (const float*)d_in[23];
    const float* ln2_g  = (const float*)d_in[24];
    const float* ln2_b  = (const float*)d_in[25];
    const float* ln3_g  = (const float*)d_in[26];
    const float* ln3_b  = (const float*)d_in[27];
    float* out = (float*)d_out;

    cudaFuncSetAttribute(gemm_std<384>,
                         cudaFuncAttributeMaxDynamicSharedMemorySize, G16_SMEM);
    cudaFuncSetAttribute(gemm_std<1536>,
                         cudaFuncAttributeMaxDynamicSharedMemorySize, G16_SMEM);
    cudaFuncSetAttribute(gemm_dual,
                         cudaFuncAttributeMaxDynamicSharedMemorySize, G16_SMEM);
    cudaFuncSetAttribute(attn16_kernel,
                         cudaFuncAttributeMaxDynamicSharedMemorySize, AT_SMEM);

    __half *pqkv, *pkv, *pq, *patt, *phid, *pxh, *pench, *po1h, *po2h;
    __half *pwqkv, *pwq2, *pwkv, *pwp1, *pwp2, *pwf1, *pwf2;
    float *pbuf, *po1, *po2, *pbqkv, *pbkv, *pbq2;
    cudaGetSymbolAddress((void**)&pqkv,  g_qkv_h);
    cudaGetSymbolAddress((void**)&pkv,   g_kv_h);
    cudaGetSymbolAddress((void**)&pq,    g_q_h);
    cudaGetSymbolAddress((void**)&patt,  g_att_h);
    cudaGetSymbolAddress((void**)&phid,  g_hid_h);
    cudaGetSymbolAddress((void**)&pxh,   g_xh);
    cudaGetSymbolAddress((void**)&pench, g_ench);
    cudaGetSymbolAddress((void**)&po1h,  g_po1h);
    cudaGetSymbolAddress((void**)&po2h,  g_po2h);
    cudaGetSymbolAddress((void**)&pbuf,  g_buf);
    cudaGetSymbolAddress((void**)&po1,   g_o1);
    cudaGetSymbolAddress((void**)&po2,   g_o2);
    cudaGetSymbolAddress((void**)&pwqkv, g_wqkvh);
    cudaGetSymbolAddress((void**)&pwq2,  g_wq2h);
    cudaGetSymbolAddress((void**)&pwkv,  g_wkvh);
    cudaGetSymbolAddress((void**)&pwp1,  g_wp1h);
    cudaGetSymbolAddress((void**)&pwp2,  g_wp2h);
    cudaGetSymbolAddress((void**)&pwf1,  g_wf1h);
    cudaGetSymbolAddress((void**)&pwf2,  g_wf2h);
    cudaGetSymbolAddress((void**)&pbqkv, g_bqkv);
    cudaGetSymbolAddress((void**)&pbkv,  g_bkv);
    cudaGetSymbolAddress((void**)&pbq2,  g_bq2);

    megapack_kernel<<<(int)((PACK_TOTAL + 255) / 256), 256>>>(
        sa1_wq, sa1_wk, sa1_wv, sa2_wq, sa2_wk, sa2_wv,
        sa1_pw, sa2_pw, ff_w1, ff_w2,
        sa1_bq, sa1_bk, sa1_bv, sa2_bq, sa2_bk, sa2_bv,
        x, enc,
        pwqkv, pwq2, pwkv, pwp1, pwp2, pwf1, pwf2,
        pbqkv, pbkv, pbq2, pxh, pench);

    // ---- fused: QKV(x) + KV(enc) in one launch (both depend only on pack) --
    gemm_dual<<<dim3(15, 128), 256, G16_SMEM>>>(
        pxh, pwqkv, pbqkv, pqkv, 3 * EE,
        pench, pwkv, pbkv, pkv, 2 * EE);

    // ---- block 1: masked self-attention + add&norm ----
    attn16_kernel<<<BB * HH * 2, 256, AT_SMEM>>>(pqkv, 3 * EE,
                                                 pqkv + EE, pqkv + 2 * EE, 3 * EE, patt);
    gemm_std<384><<<dim3(3, 128), 256, G16_SMEM>>>(
        patt, pwp1, sa1_pb, x, pbuf, nullptr, EE, 0);           // pbuf = x + proj
    ln_kernel<<<NROWS / 8, 256>>>(pbuf, ln1_g, ln1_b, po1, po1h);

    // ---- block 2: cross-attention (still causal-masked) + add&norm ----
    gemm_std<384><<<dim3(3, 128), 256, G16_SMEM>>>(
        po1h, pwq2, pbq2, nullptr, nullptr, pq, EE, 0);
    attn16_kernel<<<BB * HH * 2, 256, AT_SMEM>>>(pq, EE,
                                                 pkv, pkv + EE, 2 * EE, patt);
    gemm_std<384><<<dim3(3, 128), 256, G16_SMEM>>>(
        patt, pwp2, sa2_pb, po1, pbuf, nullptr, EE, 0);         // pbuf = o1 + proj
    ln_kernel<<<NROWS / 8, 256>>>(pbuf, ln2_g, ln2_b, po2, po2h);

    // ---- FFN + add&norm ----
    gemm_std<384><<<dim3(12, 128), 256, G16_SMEM>>>(
        po2h, pwf1, ff_b1, nullptr, nullptr, phid, FFD, 1);
    gemm_std<1536><<<dim3(3, 128), 256, G16_SMEM>>>(
        phid, pwf2, ff_b2, po2, pbuf, nullptr, EE, 0);          // pbuf = o2 + ff
    ln_kernel<<<NROWS / 8, 256>>>(pbuf, ln3_g, ln3_b, out, nullptr);
}

// round 12
// speedup vs baseline: 1.2200x; 1.0828x over previous
#include <cuda_runtime.h>
#include <cuda_fp16.h>
#include <cstdint>
#include <cstddef>

// Problem constants
#define EE   384
#define HH   6
#define HSS  64
#define BB   64
#define TT   256
#define FFD  1536
#define NROWS (BB*TT)          // 16384

// ---------------- scratch (device globals; no allocation allowed) ----------
__device__ __half g_qkv_h[(size_t)NROWS * 3 * EE];
__device__ __half g_kv_h[(size_t)NROWS * 2 * EE];
__device__ __half g_q_h[(size_t)NROWS * EE];
__device__ __half g_att_h[(size_t)NROWS * EE];
__device__ __half g_hid_h[(size_t)NROWS * FFD];
__device__ __half g_xh[(size_t)NROWS * EE];
__device__ __half g_ench[(size_t)NROWS * EE];
__device__ __half g_po1h[(size_t)NROWS * EE];
__device__ __half g_po2h[(size_t)NROWS * EE];
__device__ __half g_bufh[(size_t)NROWS * EE];
// fp16 weights, transposed to [out][in]
__device__ __half g_wqkvh[3 * EE * EE];
__device__ __half g_wq2h[EE * EE];
__device__ __half g_wkvh[2 * EE * EE];
__device__ __half g_wp1h[EE * EE];
__device__ __half g_wp2h[EE * EE];
__device__ __half g_wf1h[FFD * EE];
__device__ __half g_wf2h[EE * FFD];
__device__ float  g_bqkv[3 * EE];
__device__ float  g_bkv[2 * EE];
__device__ float  g_bq2[EE];

// ---------------- PTX helpers ----------------------------------------------
__device__ __forceinline__ uint32_t smem_u32(const void* p) {
    uint32_t a;
    asm("{ .reg .u64 t; cvta.to.shared.u64 t, %1; cvt.u32.u64 %0, t; }" : "=r"(a) : "l"(p));
    return a;
}
__device__ __forceinline__ void cp16(uint32_t dst, const void* src) {
    asm volatile("cp.async.cg.shared.global [%0], [%1], 16;" :: "r"(dst), "l"(src));
}
__device__ __forceinline__ void ldsm4(uint32_t& r0, uint32_t& r1, uint32_t& r2, uint32_t& r3,
                                      uint32_t addr) {
    asm volatile("ldmatrix.sync.aligned.m8n8.x4.shared.b16 {%0,%1,%2,%3}, [%4];"
                 : "=r"(r0), "=r"(r1), "=r"(r2), "=r"(r3) : "r"(addr));
}
__device__ __forceinline__ void ldsm4t(uint32_t& r0, uint32_t& r1, uint32_t& r2, uint32_t& r3,
                                       uint32_t addr) {
    asm volatile("ldmatrix.sync.aligned.m8n8.x4.trans.shared.b16 {%0,%1,%2,%3}, [%4];"
                 : "=r"(r0), "=r"(r1), "=r"(r2), "=r"(r3) : "r"(addr));
}
__device__ __forceinline__ void mma16816(float* c, const uint32_t* a, const uint32_t* b) {
    asm volatile(
        "mma.sync.aligned.m16n8k16.row.col.f32.f16.f16.f32 "
        "{%0,%1,%2,%3}, {%4,%5,%6,%7}, {%8,%9}, {%0,%1,%2,%3};"
        : "+f"(c[0]), "+f"(c[1]), "+f"(c[2]), "+f"(c[3])
        : "r"(a[0]), "r"(a[1]), "r"(a[2]), "r"(a[3]), "r"(b[0]), "r"(b[1]));
}
__device__ __forceinline__ uint32_t ph2(float a, float b) {
    __half2 h = __floats2half2_rn(a, b);
    return *reinterpret_cast<uint32_t*>(&h);
}
__device__ __forceinline__ uint32_t sw_off(int r, int seg) {
    return (uint32_t)(r * 128 + (((seg ^ (r & 7)) & 7) << 4));
}

// ---------------- megapack: tiled transposes + biases + act conversion -----
// block ranges (256 threads each):
#define T_A   864                   // attn weights: 6 tensors x 6 heads x 24 tiles
#define T_PW  (T_A + 288)           // pw1,pw2: 2 x 144 tiles
#define T_F1  (T_PW + 576)          // fw1: 12 x 48 tiles
#define T_F2  (T_F1 + 576)          // fw2: 48 x 12 tiles
#define B_BIAS (T_F2 + 9)           // 2304 bias elems
#define NACTV  ((long long)((size_t)NROWS * EE / 4))
#define B_ACT  (B_BIAS + 12288)     // 2 x NROWS x EE floats, float4 per thread

__global__ void __launch_bounds__(256)
megapack_kernel(
    const float* __restrict__ wq1, const float* __restrict__ wk1, const float* __restrict__ wv1,
    const float* __restrict__ wq2, const float* __restrict__ wk2, const float* __restrict__ wv2,
    const float* __restrict__ pw1, const float* __restrict__ pw2,
    const float* __restrict__ fw1, const float* __restrict__ fw2,
    const float* __restrict__ bq1, const float* __restrict__ bk1, const float* __restrict__ bv1,
    const float* __restrict__ bq2, const float* __restrict__ bk2, const float* __restrict__ bv2,
    const float* __restrict__ x, const float* __restrict__ enc,
    __half* __restrict__ wqkv, __half* __restrict__ wqo, __half* __restrict__ wkv,
    __half* __restrict__ wp1o, __half* __restrict__ wp2o,
    __half* __restrict__ wf1o, __half* __restrict__ wf2o,
    float* __restrict__ bqkv, float* __restrict__ bkv, float* __restrict__ bq2o,
    __half* __restrict__ xh, __half* __restrict__ ench)
{
    int bid = blockIdx.x, tid = threadIdx.x;
    if (bid < T_F2) {
        __shared__ float ttile[32][33];
        const float* src; __half* dst;
        int lds, ldd, r0, c0;
        float scale = 1.0f;
        if (bid < T_A) {
            int tensor = bid / 144, rem = bid % 144;
            int h = rem / 24, t = rem % 24;
            r0 = (t >> 1) * 32; c0 = (t & 1) * 32;
            const float* srcs[6] = {wq1, wk1, wv1, wq2, wk2, wv2};
            src = srcs[tensor] + (size_t)h * EE * HSS;
            lds = HSS; ldd = EE;
            int rowoff;
            if (tensor < 3)       { dst = wqkv; rowoff = tensor * EE; }
            else if (tensor == 3) { dst = wqo;  rowoff = 0; }
            else                  { dst = wkv;  rowoff = (tensor - 4) * EE; }
            dst += (size_t)(rowoff + h * HSS) * EE;
            if (tensor == 0 || tensor == 3) scale = rsqrtf((float)EE);
        } else if (bid < T_PW) {
            int j = bid - T_A, which = j / 144, t = j % 144;
            r0 = (t / 12) * 32; c0 = (t % 12) * 32;
            src = which ? pw2 : pw1; dst = which ? wp2o : wp1o;
            lds = EE; ldd = EE;
        } else if (bid < T_F1) {
            int t = bid - T_PW;
            r0 = (t / 48) * 32; c0 = (t % 48) * 32;
            src = fw1; dst = wf1o; lds = FFD; ldd = EE;
        } else {
            int t = bid - T_F1;
            r0 = (t / 12) * 32; c0 = (t % 12) * 32;
            src = fw2; dst = wf2o; lds = EE; ldd = FFD;
        }
        int tx = tid & 31, ty = tid >> 5;
#pragma unroll
        for (int i = 0; i < 4; i++) {
            int row = ty + i * 8;
            ttile[row][tx] = src[(size_t)(r0 + row) * lds + c0 + tx] * scale;
        }
        __syncthreads();
#pragma unroll
        for (int i = 0; i < 4; i++) {
            int row = ty + i * 8;
            dst[(size_t)(c0 + row) * ldd + r0 + tx] = __float2half_rn(ttile[tx][row]);
        }
        return;
    }
    if (bid < B_BIAS) {
        int i = (bid - T_F2) * 256 + tid;
        float scale = rsqrtf((float)EE);
        if (i < 3 * EE) {
            int sub = i / EE, jj = i % EE;
            bqkv[i] = sub == 0 ? bq1[jj] * scale : sub == 1 ? bk1[jj] : bv1[jj];
        } else if (i < 5 * EE) {
            int k = i - 3 * EE;
            bkv[k] = k < EE ? bk2[k] : bv2[k - EE];
        } else {
            int k = i - 5 * EE;
            bq2o[k] = bq2[k] * scale;
        }
        return;
    }
    long long ai = (long long)(bid - B_BIAS) * 256 + tid;   // float4 index
    const float* srcf; __half* dsth;
    if (ai < NACTV) { srcf = x; dsth = xh; }
    else { ai -= NACTV; srcf = enc; dsth = ench; }
    float4 v4 = ((const float4*)srcf)[ai];
    ((__half2*)dsth)[2 * ai]     = __floats2half2_rn(v4.x, v4.y);
    ((__half2*)dsth)[2 * ai + 1] = __floats2half2_rn(v4.z, v4.w);
}

// ---------------- fp16 tensor-core GEMM body (128x128 tile, BK=64) ----------
#define G16_SMEM (3 * 32768)

template <int K>
__device__ __forceinline__ void load_chunk(uint32_t sbase,
                                           const __half* __restrict__ A,
                                           const __half* __restrict__ Wt,
                                           int row0, int col0, int tid,
                                           int stage, int kt) {
    uint32_t sA = sbase + (uint32_t)stage * 32768u;
    uint32_t sB = sA + 16384u;
#pragma unroll
    for (int i = 0; i < 4; i++) {
        int li = tid + i * 256; int r = li >> 3, sg = li & 7;
        cp16(sA + sw_off(r, sg), A + (size_t)(row0 + r) * K + kt + sg * 8);
        cp16(sB + sw_off(r, sg), Wt + (size_t)(col0 + r) * K + kt + sg * 8);
    }
    asm volatile("cp.async.commit_group;");
}

template <int K>
__device__ __forceinline__ void gemm_body(const __half* __restrict__ A,
                                          const __half* __restrict__ Wt,
                                          const float* __restrict__ bias,
                                          const __half* __restrict__ resid,
                                          __half* __restrict__ Ch,
                                          int M, int relu, int colt, int rowt,
                                          char* gsm)
{
    uint32_t sbase = smem_u32(gsm);
    int tid = threadIdx.x, lane = tid & 31, warp = tid >> 5;
    int wm = warp >> 2, wn = warp & 3;
    int gid = lane >> 2, tg = lane & 3;
    int j = lane >> 3, rr = lane & 7;
    int col0 = colt * 128, row0 = rowt * 128;

    float acc[4][4][4];
#pragma unroll
    for (int a = 0; a < 4; a++)
#pragma unroll
        for (int b = 0; b < 4; b++)
#pragma unroll
            for (int c = 0; c < 4; c++) acc[a][b][c] = 0.0f;

    constexpr int nch = K >> 6;
    load_chunk<K>(sbase, A, Wt, row0, col0, tid, 0, 0);
    load_chunk<K>(sbase, A, Wt, row0, col0, tid, 1, 64);

#pragma unroll 2
    for (int it = 0; it < nch; it++) {
        if (it + 1 < nch) asm volatile("cp.async.wait_group 1;");
        else              asm volatile("cp.async.wait_group 0;");
        __syncthreads();
        if (it + 2 < nch)
            load_chunk<K>(sbase, A, Wt, row0, col0, tid, (it + 2) % 3, (it + 2) * 64);
        uint32_t sA = sbase + (uint32_t)(it % 3) * 32768u;
        uint32_t sB = sA + 16384u;
#pragma unroll
        for (int ks = 0; ks < 4; ks++) {
            uint32_t a[4][4], bfr[2][4];
#pragma unroll
            for (int mt = 0; mt < 4; mt++)
                ldsm4(a[mt][0], a[mt][1], a[mt][2], a[mt][3],
                      sA + sw_off(wm * 64 + mt * 16 + (j & 1) * 8 + rr, ks * 2 + (j >> 1)));
#pragma unroll
            for (int p = 0; p < 2; p++)
                ldsm4(bfr[p][0], bfr[p][1], bfr[p][2], bfr[p][3],
                      sB + sw_off(wn * 32 + p * 16 + (j >> 1) * 8 + rr, ks * 2 + (j & 1)));
#pragma unroll
            for (int mt = 0; mt < 4; mt++)
#pragma unroll
                for (int nt = 0; nt < 4; nt++)
                    mma16816(acc[mt][nt], a[mt], &bfr[nt >> 1][(nt & 1) * 2]);
        }
    }

#pragma unroll
    for (int mt = 0; mt < 4; mt++)
#pragma unroll
        for (int nt = 0; nt < 4; nt++) {
            int r0 = row0 + wm * 64 + mt * 16 + gid;
            int c0 = col0 + wn * 32 + nt * 8 + tg * 2;
            float b0 = bias[c0], b1 = bias[c0 + 1];
            float v0 = acc[mt][nt][0] + b0, v1 = acc[mt][nt][1] + b1;
            float v2 = acc[mt][nt][2] + b0, v3 = acc[mt][nt][3] + b1;
            if (resid) {
                float2 ra = __half22float2(*(const __half2*)(resid + (size_t)r0 * M + c0));
                float2 rb = __half22float2(*(const __half2*)(resid + (size_t)(r0 + 8) * M + c0));
                v0 += ra.x; v1 += ra.y; v2 += rb.x; v3 += rb.y;
            }
            if (relu) {
                v0 = fmaxf(v0, 0.f); v1 = fmaxf(v1, 0.f);
                v2 = fmaxf(v2, 0.f); v3 = fmaxf(v3, 0.f);
            }
            *(__half2*)(Ch + (size_t)r0 * M + c0)       = __floats2half2_rn(v0, v1);
            *(__half2*)(Ch + (size_t)(r0 + 8) * M + c0) = __floats2half2_rn(v2, v3);
        }
}

template <int K>
__global__ void __launch_bounds__(256, 2)
gemm_std(const __half* __restrict__ A, const __half* __restrict__ Wt,
         const float* __restrict__ bias, const __half* __restrict__ resid,
         __half* __restrict__ Ch, int M, int relu)
{
    extern __shared__ char gsm[];
    gemm_body<K>(A, Wt, bias, resid, Ch, M, relu, blockIdx.x, blockIdx.y, gsm);
}

// merged: two independent K=384 GEMMs in one launch (128-col tiles)
__global__ void __launch_bounds__(256, 2)
gemm_dual(const __half* __restrict__ A1, const __half* __restrict__ W1,
          const float* __restrict__ b1, __half* __restrict__ C1, int M1,
          const __half* __restrict__ A2, const __half* __restrict__ W2,
          const float* __restrict__ b2, __half* __restrict__ C2, int M2)
{
    extern __shared__ char gsm[];
    int t1 = M1 / 128;
    if ((int)blockIdx.x < t1)
        gemm_body<384>(A1, W1, b1, nullptr, C1, M1, 0, blockIdx.x, blockIdx.y, gsm);
    else
        gemm_body<384>(A2, W2, b2, nullptr, C2, M2, 0, blockIdx.x - t1, blockIdx.y, gsm);
}

// ---------------- flash attention: 128 q-rows per CTA, 8 warps --------------
#define AT_SMEM (16384 + 2 * 16384)

__global__ void __launch_bounds__(256, 2)
attn16_kernel(const __half* __restrict__ Qg, int ldq,
              const __half* __restrict__ Kg, const __half* __restrict__ Vg, int ldkv,
              __half* __restrict__ Og)
{
    extern __shared__ __align__(128) char asmem[];
    uint32_t sbase = smem_u32(asmem);
    uint32_t sQ = sbase;
    int tid = threadIdx.x, lane = tid & 31, w = tid >> 5;
    int gid = lane >> 2, tg = lane & 3;
    int j = lane >> 3, rr = lane & 7;

    int bid = blockIdx.x;
    int qt = (bid & 1) ^ 1;            // heavy tiles (qt=1) scheduled first
    int h = (bid >> 1) % HH, b = bid / (2 * HH);
    int t0 = qt * 128;
    int hoff = h * HSS;

    const __half* qrow = Qg + (size_t)(b * TT + t0) * ldq + hoff;
#pragma unroll
    for (int i = 0; i < 4; i++) {
        int li = tid + i * 256; int r = li >> 3, sg = li & 7;
        cp16(sQ + sw_off(r, sg), qrow + (size_t)r * ldq + sg * 8);
    }
#define KVLOAD(ut, bufi)                                                           \
    {                                                                              \
        uint32_t sK_ = sbase + 16384u + (uint32_t)(bufi) * 16384u;                 \
        uint32_t sV_ = sK_ + 8192u;                                                \
        const __half* kr = Kg + (size_t)(b * TT + (ut) * 64) * ldkv + hoff;        \
        const __half* vr = Vg + (size_t)(b * TT + (ut) * 64) * ldkv + hoff;        \
        _Pragma("unroll")                                                          \
        for (int i = 0; i < 2; i++) {                                              \
            int li = tid + i * 256; int r = li >> 3, sg = li & 7;                  \
            cp16(sK_ + sw_off(r, sg), kr + (size_t)r * ldkv + sg * 8);             \
            cp16(sV_ + sw_off(r, sg), vr + (size_t)r * ldkv + sg * 8);             \
        }                                                                          \
        asm volatile("cp.async.commit_group;");                                    \
    }
    KVLOAD(0, 0);
    asm volatile("cp.async.wait_group 0;");
    __syncthreads();

    uint32_t qf[4][4];
#pragma unroll
    for (int ks = 0; ks < 4; ks++)
        ldsm4(qf[ks][0], qf[ks][1], qf[ks][2], qf[ks][3],
              sQ + sw_off(w * 16 + (j & 1) * 8 + rr, ks * 2 + (j >> 1)));

    float o[8][4];
#pragma unroll
    for (int nt = 0; nt < 8; nt++)
#pragma unroll
        for (int e = 0; e < 4; e++) o[nt][e] = 0.0f;
    float m0 = -1e30f, m1 = -1e30f, l0 = 0.0f, l1 = 0.0f;

    int nkv = 2 * (qt + 1);
    int r0g = t0 + w * 16 + gid;
    for (int ut = 0; ut < nkv; ut++) {
        if (ut > 0) { asm volatile("cp.async.wait_group 0;"); __syncthreads(); }
        if (ut < nkv - 1) KVLOAD(ut + 1, (ut + 1) & 1);
        uint32_t sK = sbase + 16384u + (uint32_t)(ut & 1) * 16384u;
        uint32_t sV = sK + 8192u;

        float s[8][4];
#pragma unroll
        for (int nt = 0; nt < 8; nt++)
#pragma unroll
            for (int e = 0; e < 4; e++) s[nt][e] = 0.0f;
#pragma unroll
        for (int ks = 0; ks < 4; ks++) {
            uint32_t kb[4][4];
#pragma unroll
            for (int p = 0; p < 4; p++)
                ldsm4(kb[p][0], kb[p][1], kb[p][2], kb[p][3],
                      sK + sw_off(p * 16 + (j >> 1) * 8 + rr, ks * 2 + (j & 1)));
#pragma unroll
            for (int nt = 0; nt < 8; nt++)
                mma16816(s[nt], qf[ks], &kb[nt >> 1][(nt & 1) * 2]);
        }
        if (ut >= 2 * qt) {
#pragma unroll
            for (int nt = 0; nt < 8; nt++) {
                int u0 = ut * 64 + nt * 8 + tg * 2;
                if (u0     > r0g)     s[nt][0] = -1e30f;
                if (u0 + 1 > r0g)     s[nt][1] = -1e30f;
                if (u0     > r0g + 8) s[nt][2] = -1e30f;
                if (u0 + 1 > r0g + 8) s[nt][3] = -1e30f;
            }
        }
        float mx0 = -1e30f, mx1 = -1e30f;
#pragma unroll
        for (int nt = 0; nt < 8; nt++) {
            mx0 = fmaxf(mx0, fmaxf(s[nt][0], s[nt][1]));
            mx1 = fmaxf(mx1, fmaxf(s[nt][2], s[nt][3]));
        }
        mx0 = fmaxf(mx0, __shfl_xor_sync(~0u, mx0, 1));
        mx0 = fmaxf(mx0, __shfl_xor_sync(~0u, mx0, 2));
        mx1 = fmaxf(mx1, __shfl_xor_sync(~0u, mx1, 1));
        mx1 = fmaxf(mx1, __shfl_xor_sync(~0u, mx1, 2));
        float mn0 = fmaxf(m0, mx0), mn1 = fmaxf(m1, mx1);
        float f0 = __expf(m0 - mn0), f1 = __expf(m1 - mn1);
        m0 = mn0; m1 = mn1;
        float rs0 = 0.0f, rs1 = 0.0f;
#pragma unroll
        for (int nt = 0; nt < 8; nt++) {
            s[nt][0] = __expf(s[nt][0] - mn0); rs0 += s[nt][0];
            s[nt][1] = __expf(s[nt][1] - mn0); rs0 += s[nt][1];
            s[nt][2] = __expf(s[nt][2] - mn1); rs1 += s[nt][2];
            s[nt][3] = __expf(s[nt][3] - mn1); rs1 += s[nt][3];
        }
        rs0 += __shfl_xor_sync(~0u, rs0, 1); rs0 += __shfl_xor_sync(~0u, rs0, 2);
        rs1 += __shfl_xor_sync(~0u, rs1, 1); rs1 += __shfl_xor_sync(~0u, rs1, 2);
        l0 = l0 * f0 + rs0;
        l1 = l1 * f1 + rs1;
#pragma unroll
        for (int nt = 0; nt < 8; nt++) {
            o[nt][0] *= f0; o[nt][1] *= f0; o[nt][2] *= f1; o[nt][3] *= f1;
        }
        uint32_t pa[4][4];
#pragma unroll
        for (int kk = 0; kk < 4; kk++) {
            pa[kk][0] = ph2(s[2 * kk][0], s[2 * kk][1]);
            pa[kk][1] = ph2(s[2 * kk][2], s[2 * kk][3]);
            pa[kk][2] = ph2(s[2 * kk + 1][0], s[2 * kk + 1][1]);
            pa[kk][3] = ph2(s[2 * kk + 1][2], s[2 * kk + 1][3]);
        }
#pragma unroll
        for (int kk = 0; kk < 4; kk++) {
            uint32_t vb[4][4];
#pragma unroll
            for (int p = 0; p < 4; p++)
                ldsm4t(vb[p][0], vb[p][1], vb[p][2], vb[p][3],
                       sV + sw_off(kk * 16 + (j & 1) * 8 + rr, p * 2 + (j >> 1)));
#pragma unroll
            for (int nt = 0; nt < 8; nt++)
                mma16816(o[nt], pa[kk], &vb[nt >> 1][(nt & 1) * 2]);
        }
    }
    float i0 = 1.0f / l0, i1 = 1.0f / l1;
    __half* orow = Og + (size_t)(b * TT + t0) * EE + hoff;
#pragma unroll
    for (int nt = 0; nt < 8; nt++) {
        int c = nt * 8 + tg * 2;
        *(__half2*)(orow + (size_t)(w * 16 + gid) * EE + c) =
            __floats2half2_rn(o[nt][0] * i0, o[nt][1] * i0);
        *(__half2*)(orow + (size_t)(w * 16 + gid + 8) * EE + c) =
            __floats2half2_rn(o[nt][2] * i1, o[nt][3] * i1);
    }
}

// ---------------- LayerNorm: fp16 in, one warp per row, shuffle-only --------
__global__ void __launch_bounds__(256)
ln_kernel(const __half* __restrict__ s_in,
          const float* __restrict__ g, const float* __restrict__ bt,
          __half* __restrict__ oh, float* __restrict__ of) {
    int warp = threadIdx.x >> 5, lane = threadIdx.x & 31;
    int row = blockIdx.x * 8 + warp;
    const uint2* rp = (const uint2*)(s_in + (size_t)row * EE);
    float v[3][4];
#pragma unroll
    for (int i = 0; i < 3; i++) {
        uint2 raw = rp[lane + 32 * i];
        float2 f0 = __half22float2(*reinterpret_cast<__half2*>(&raw.x));
        float2 f1 = __half22float2(*reinterpret_cast<__half2*>(&raw.y));
        v[i][0] = f0.x; v[i][1] = f0.y; v[i][2] = f1.x; v[i][3] = f1.y;
    }
    float s = 0.0f;
#pragma unroll
    for (int i = 0; i < 3; i++) s += v[i][0] + v[i][1] + v[i][2] + v[i][3];
#pragma unroll
    for (int off = 16; off; off >>= 1) s += __shfl_xor_sync(~0u, s, off);
    float mean = s * (1.0f / EE);
    float sq = 0.0f;
#pragma unroll
    for (int i = 0; i < 3; i++) {
        float a0 = v[i][0] - mean, a1 = v[i][1] - mean;
        float a2 = v[i][2] - mean, a3 = v[i][3] - mean;
        sq += a0 * a0 + a1 * a1 + a2 * a2 + a3 * a3;
    }
#pragma unroll
    for (int off = 16; off; off >>= 1) sq += __shfl_xor_sync(~0u, sq, off);
    float inv = rsqrtf(sq * (1.0f / EE) + 1e-5f);
    uint2* ohp = oh ? (uint2*)(oh + (size_t)row * EE) : nullptr;
    float4* ofp = of ? (float4*)(of + (size_t)row * EE) : nullptr;
#pragma unroll
    for (int i = 0; i < 3; i++) {
        int e4 = lane + 32 * i;
        float4 gg = *(const float4*)(g + e4 * 4);
        float4 bb = *(const float4*)(bt + e4 * 4);
        float r0 = (v[i][0] - mean) * inv * gg.x + bb.x;
        float r1 = (v[i][1] - mean) * inv * gg.y + bb.y;
        float r2 = (v[i][2] - mean) * inv * gg.z + bb.z;
        float r3 = (v[i][3] - mean) * inv * gg.w + bb.w;
        if (ohp) {
            uint2 pk;
            pk.x = ph2(r0, r1);
            pk.y = ph2(r2, r3);
            ohp[e4] = pk;
        }
        if (ofp) ofp[e4] = make_float4(r0, r1, r2, r3);
    }
}

// ---------------- host orchestration ---------------------------------------
extern "C" void kernel_launch(void* const* d_in, const int* in_sizes, int n_in,
                              void* d_out, int out_size) {
    const float* enc = (const float*)d_in[0];
    const float* x   = (const float*)d_in[1];
    const float* sa1_wq = (const float*)d_in[2];
    const float* sa1_bq = (const float*)d_in[3];
    const float* sa1_wk = (const float*)d_in[4];
    const float* sa1_bk = (const float*)d_in[5];
    const float* sa1_wv = (const float*)d_in[6];
    const float* sa1_bv = (const float*)d_in[7];
    const float* sa1_pw = (const float*)d_in[8];
    const float* sa1_pb = (const float*)d_in[9];
    const float* sa2_wq = (const float*)d_in[10];
    const float* sa2_bq = (const float*)d_in[11];
    const float* sa2_wk = (const float*)d_in[12];
    const float* sa2_bk = (const float*)d_in[13];
    const float* sa2_wv = (const float*)d_in[14];
    const float* sa2_bv = (const float*)d_in[15];
    const float* sa2_pw = (const float*)d_in[16];
    const float* sa2_pb = (const float*)d_in[17];
    const float* ff_w1  = (const float*)d_in[18];
    const float* ff_b1  = (const float*)d_in[19];
    const float* ff_w2  = (const float*)d_in[20];
    const float* ff_b2  = (const float*)d_in[21];
    const float* ln1_g  = (const float*)d_in[22];
    const float* ln1_b  = (const float*)d_in[23];
    const float* ln2_g  = (const float*)d_in[24];
    const float* ln2_b  = (const float*)d_in[25];
    const float* ln3_g  = (const float*)d_in[26];
    const float* ln3_b  = (const float*)d_in[27];
    float* out = (float*)d_out;

    cudaFuncSetAttribute(gemm_std<384>,
                         cudaFuncAttributeMaxDynamicSharedMemorySize, G16_SMEM);
    cudaFuncSetAttribute(gemm_std<1536>,
                         cudaFuncAttributeMaxDynamicSharedMemorySize, G16_SMEM);
    cudaFuncSetAttribute(gemm_dual,
                         cudaFuncAttributeMaxDynamicSharedMemorySize, G16_SMEM);
    cudaFuncSetAttribute(attn16_kernel,
                         cudaFuncAttributeMaxDynamicSharedMemorySize, AT_SMEM);

    __half *pqkv, *pkv, *pq, *patt, *phid, *pxh, *pench, *po1h, *po2h, *pbufh;
    __half *pwqkv, *pwq2, *pwkv, *pwp1, *pwp2, *pwf1, *pwf2;
    float *pbqkv, *pbkv, *pbq2;
    cudaGetSymbolAddress((void**)&pqkv,  g_qkv_h);
    cudaGetSymbolAddress((void**)&pkv,   g_kv_h);
    cudaGetSymbolAddress((void**)&pq,    g_q_h);
    cudaGetSymbolAddress((void**)&patt,  g_att_h);
    cudaGetSymbolAddress((void**)&phid,  g_hid_h);
    cudaGetSymbolAddress((void**)&pxh,   g_xh);
    cudaGetSymbolAddress((void**)&pench, g_ench);
    cudaGetSymbolAddress((void**)&po1h,  g_po1h);
    cudaGetSymbolAddress((void**)&po2h,  g_po2h);
    cudaGetSymbolAddress((void**)&pbufh, g_bufh);
    cudaGetSymbolAddress((void**)&pwqkv, g_wqkvh);
    cudaGetSymbolAddress((void**)&pwq2,  g_wq2h);
    cudaGetSymbolAddress((void**)&pwkv,  g_wkvh);
    cudaGetSymbolAddress((void**)&pwp1,  g_wp1h);
    cudaGetSymbolAddress((void**)&pwp2,  g_wp2h);
    cudaGetSymbolAddress((void**)&pwf1,  g_wf1h);
    cudaGetSymbolAddress((void**)&pwf2,  g_wf2h);
    cudaGetSymbolAddress((void**)&pbqkv, g_bqkv);
    cudaGetSymbolAddress((void**)&pbkv,  g_bkv);
    cudaGetSymbolAddress((void**)&pbq2,  g_bq2);

    megapack_kernel<<<B_ACT, 256>>>(
        sa1_wq, sa1_wk, sa1_wv, sa2_wq, sa2_wk, sa2_wv,
        sa1_pw, sa2_pw, ff_w1, ff_w2,
        sa1_bq, sa1_bk, sa1_bv, sa2_bq, sa2_bk, sa2_bv,
        x, enc,
        pwqkv, pwq2, pwkv, pwp1, pwp2, pwf1, pwf2,
        pbqkv, pbkv, pbq2, pxh, pench);

    // ---- fused: QKV(x) + KV(enc) in one launch ----
    gemm_dual<<<dim3(15, 128), 256, G16_SMEM>>>(
        pxh, pwqkv, pbqkv, pqkv, 3 * EE,
        pench, pwkv, pbkv, pkv, 2 * EE);

    // ---- block 1: masked self-attention + add&norm ----
    attn16_kernel<<<BB * HH * 2, 256, AT_SMEM>>>(pqkv, 3 * EE,
                                                 pqkv + EE, pqkv + 2 * EE, 3 * EE, patt);
    gemm_std<384><<<dim3(3, 128), 256, G16_SMEM>>>(
        patt, pwp1, sa1_pb, pxh, pbufh, EE, 0);                 // bufh = x + proj
    ln_kernel<<<NROWS / 8, 256>>>(pbufh, ln1_g, ln1_b, po1h, nullptr);

    // ---- block 2: cross-attention (still causal-masked) + add&norm ----
    gemm_std<384><<<dim3(3, 128), 256, G16_SMEM>>>(
        po1h, pwq2, pbq2, nullptr, pq, EE, 0);
    attn16_kernel<<<BB * HH * 2, 256, AT_SMEM>>>(pq, EE,
                                                 pkv, pkv + EE, 2 * EE, patt);
    gemm_std<384><<<dim3(3, 128), 256, G16_SMEM>>>(
        patt, pwp2, sa2_pb, po1h, pbufh, EE, 0);                // bufh = o1 + proj
    ln_kernel<<<NROWS / 8, 256>>>(pbufh, ln2_g, ln2_b, po2h, nullptr);

    // ---- FFN + add&norm ----
    gemm_std<384><<<dim3(12, 128), 256, G16_SMEM>>>(
        po2h, pwf1, ff_b1, nullptr, phid, FFD, 1);
    gemm_std<1536><<<dim3(3, 128), 256, G16_SMEM>>>(
        phid, pwf2, ff_b2, po2h, pbufh, EE, 0);                 // bufh = o2 + ff
    ln_kernel<<<NROWS / 8, 256>>>(pbufh, ln3_g, ln3_b, nullptr, out);
}

// round 13
// speedup vs baseline: 1.2326x; 1.0104x over previous
#include <cuda_runtime.h>
#include <cuda_fp16.h>
#include <cstdint>
#include <cstddef>

// Problem constants
#define EE   384
#define HH   6
#define HSS  64
#define BB   64
#define TT   256
#define FFD  1536
#define NROWS (BB*TT)          // 16384

// ---------------- scratch (device globals; no allocation allowed) ----------
__device__ __half g_qkv_h[(size_t)NROWS * 3 * EE];
__device__ __half g_kv_h[(size_t)NROWS * 2 * EE];
__device__ __half g_q_h[(size_t)NROWS * EE];
__device__ __half g_att_h[(size_t)NROWS * EE];
__device__ __half g_hid_h[(size_t)NROWS * FFD];
__device__ __half g_xh[(size_t)NROWS * EE];
__device__ __half g_ench[(size_t)NROWS * EE];
__device__ __half g_po1h[(size_t)NROWS * EE];
__device__ __half g_po2h[(size_t)NROWS * EE];
__device__ __half g_bufh[(size_t)NROWS * EE];
// fp16 weights, transposed to [out][in]
__device__ __half g_wqkvh[3 * EE * EE];
__device__ __half g_wq2h[EE * EE];
__device__ __half g_wkvh[2 * EE * EE];
__device__ __half g_wp1h[EE * EE];
__device__ __half g_wp2h[EE * EE];
__device__ __half g_wf1h[FFD * EE];
__device__ __half g_wf2h[EE * FFD];
__device__ float  g_bqkv[3 * EE];
__device__ float  g_bkv[2 * EE];
__device__ float  g_bq2[EE];

// ---------------- PTX helpers ----------------------------------------------
__device__ __forceinline__ uint32_t smem_u32(const void* p) {
    uint32_t a;
    asm("{ .reg .u64 t; cvta.to.shared.u64 t, %1; cvt.u32.u64 %0, t; }" : "=r"(a) : "l"(p));
    return a;
}
__device__ __forceinline__ void cp16(uint32_t dst, const void* src) {
    asm volatile("cp.async.cg.shared.global [%0], [%1], 16;" :: "r"(dst), "l"(src));
}
__device__ __forceinline__ void ldsm4(uint32_t& r0, uint32_t& r1, uint32_t& r2, uint32_t& r3,
                                      uint32_t addr) {
    asm volatile("ldmatrix.sync.aligned.m8n8.x4.shared.b16 {%0,%1,%2,%3}, [%4];"
                 : "=r"(r0), "=r"(r1), "=r"(r2), "=r"(r3) : "r"(addr));
}
__device__ __forceinline__ void ldsm4t(uint32_t& r0, uint32_t& r1, uint32_t& r2, uint32_t& r3,
                                       uint32_t addr) {
    asm volatile("ldmatrix.sync.aligned.m8n8.x4.trans.shared.b16 {%0,%1,%2,%3}, [%4];"
                 : "=r"(r0), "=r"(r1), "=r"(r2), "=r"(r3) : "r"(addr));
}
__device__ __forceinline__ void mma16816(float* c, const uint32_t* a, const uint32_t* b) {
    asm volatile(
        "mma.sync.aligned.m16n8k16.row.col.f32.f16.f16.f32 "
        "{%0,%1,%2,%3}, {%4,%5,%6,%7}, {%8,%9}, {%0,%1,%2,%3};"
        : "+f"(c[0]), "+f"(c[1]), "+f"(c[2]), "+f"(c[3])
        : "r"(a[0]), "r"(a[1]), "r"(a[2]), "r"(a[3]), "r"(b[0]), "r"(b[1]));
}
__device__ __forceinline__ uint32_t ph2(float a, float b) {
    __half2 h = __floats2half2_rn(a, b);
    return *reinterpret_cast<uint32_t*>(&h);
}
__device__ __forceinline__ uint32_t sw_off(int r, int seg) {
    return (uint32_t)(r * 128 + (((seg ^ (r & 7)) & 7) << 4));
}

// ---------------- shared 32x32 transpose tile -------------------------------
__device__ __forceinline__ void transpose32(const float* __restrict__ src, int lds,
                                            __half* __restrict__ dst, int ldd,
                                            int r0, int c0, float scale, int tid) {
    __shared__ float ttile[32][33];
    int tx = tid & 31, ty = tid >> 5;
#pragma unroll
    for (int i = 0; i < 4; i++) {
        int row = ty + i * 8;
        ttile[row][tx] = src[(size_t)(r0 + row) * lds + c0 + tx] * scale;
    }
    __syncthreads();
#pragma unroll
    for (int i = 0; i < 4; i++) {
        int row = ty + i * 8;
        dst[(size_t)(c0 + row) * ldd + r0 + tx] = __float2half_rn(ttile[tx][row]);
    }
}

// ---------------- packA: critical path (attn qkv/kv weights, biases, acts) --
#define PA_T   720                  // 5 tensors x 6 heads x 24 tiles
#define PA_B   (PA_T + 9)           // 2304 bias elems
#define NACTV  ((long long)((size_t)NROWS * EE / 4))
#define PA_TOTAL (PA_B + 12288)

__global__ void __launch_bounds__(256)
packA_kernel(
    const float* __restrict__ wq1, const float* __restrict__ wk1, const float* __restrict__ wv1,
    const float* __restrict__ wk2, const float* __restrict__ wv2,
    const float* __restrict__ bq1, const float* __restrict__ bk1, const float* __restrict__ bv1,
    const float* __restrict__ bq2, const float* __restrict__ bk2, const float* __restrict__ bv2,
    const float* __restrict__ x, const float* __restrict__ enc,
    __half* __restrict__ wqkv, __half* __restrict__ wkv,
    float* __restrict__ bqkv, float* __restrict__ bkv, float* __restrict__ bq2o,
    __half* __restrict__ xh, __half* __restrict__ ench)
{
    int bid = blockIdx.x, tid = threadIdx.x;
    if (bid < PA_T) {
        int tensor = bid / 144, rem = bid % 144;
        int h = rem / 24, t = rem % 24;
        int r0 = (t >> 1) * 32, c0 = (t & 1) * 32;
        const float* srcs[5] = {wq1, wk1, wv1, wk2, wv2};
        const float* src = srcs[tensor] + (size_t)h * EE * HSS;
        __half* dst; int rowoff;
        if (tensor < 3) { dst = wqkv; rowoff = tensor * EE; }
        else            { dst = wkv;  rowoff = (tensor - 3) * EE; }
        dst += (size_t)(rowoff + h * HSS) * EE;
        float scale = (tensor == 0) ? rsqrtf((float)EE) : 1.0f;
        transpose32(src, HSS, dst, EE, r0, c0, scale, tid);
        return;
    }
    if (bid < PA_B) {
        int i = (bid - PA_T) * 256 + tid;
        float scale = rsqrtf((float)EE);
        if (i < 3 * EE) {
            int sub = i / EE, jj = i % EE;
            bqkv[i] = sub == 0 ? bq1[jj] * scale : sub == 1 ? bk1[jj] : bv1[jj];
        } else if (i < 5 * EE) {
            int k = i - 3 * EE;
            bkv[k] = k < EE ? bk2[k] : bv2[k - EE];
        } else {
            int k = i - 5 * EE;
            bq2o[k] = bq2[k] * scale;
        }
        return;
    }
    long long ai = (long long)(bid - PA_B) * 256 + tid;
    const float* srcf; __half* dsth;
    if (ai < NACTV) { srcf = x; dsth = xh; }
    else { ai -= NACTV; srcf = enc; dsth = ench; }
    float4 v4 = ((const float4*)srcf)[ai];
    ((__half2*)dsth)[2 * ai]     = __floats2half2_rn(v4.x, v4.y);
    ((__half2*)dsth)[2 * ai + 1] = __floats2half2_rn(v4.z, v4.w);
}

// ---------------- packB: off-critical-path weight transposes ----------------
#define PB_WQ2 144
#define PB_PW  (PB_WQ2 + 288)
#define PB_F1  (PB_PW + 576)
#define PB_TOTAL (PB_F1 + 576)

__global__ void __launch_bounds__(256)
packB_kernel(const float* __restrict__ wq2,
             const float* __restrict__ pw1, const float* __restrict__ pw2,
             const float* __restrict__ fw1, const float* __restrict__ fw2,
             __half* __restrict__ wqo, __half* __restrict__ wp1o, __half* __restrict__ wp2o,
             __half* __restrict__ wf1o, __half* __restrict__ wf2o)
{
    int bid = blockIdx.x, tid = threadIdx.x;
    if (bid < PB_WQ2) {
        int h = bid / 24, t = bid % 24;
        int r0 = (t >> 1) * 32, c0 = (t & 1) * 32;
        transpose32(wq2 + (size_t)h * EE * HSS, HSS,
                    wqo + (size_t)(h * HSS) * EE, EE,
                    r0, c0, rsqrtf((float)EE), tid);
    } else if (bid < PB_PW) {
        int j = bid - PB_WQ2, which = j / 144, t = j % 144;
        int r0 = (t / 12) * 32, c0 = (t % 12) * 32;
        transpose32(which ? pw2 : pw1, EE, which ? wp2o : wp1o, EE, r0, c0, 1.0f, tid);
    } else if (bid < PB_F1) {
        int t = bid - PB_PW;
        int r0 = (t / 48) * 32, c0 = (t % 48) * 32;
        transpose32(fw1, FFD, wf1o, EE, r0, c0, 1.0f, tid);
    } else {
        int t = bid - PB_F1;
        int r0 = (t / 12) * 32, c0 = (t % 12) * 32;
        transpose32(fw2, EE, wf2o, FFD, r0, c0, 1.0f, tid);
    }
}

// ---------------- fp16 tensor-core GEMM body (128x128 tile, BK=64) ----------
#define G16_SMEM (3 * 32768)

template <int K>
__device__ __forceinline__ void load_chunk(uint32_t sbase,
                                           const __half* __restrict__ A,
                                           const __half* __restrict__ Wt,
                                           int row0, int col0, int tid,
                                           int stage, int kt) {
    uint32_t sA = sbase + (uint32_t)stage * 32768u;
    uint32_t sB = sA + 16384u;
#pragma unroll
    for (int i = 0; i < 4; i++) {
        int li = tid + i * 256; int r = li >> 3, sg = li & 7;
        cp16(sA + sw_off(r, sg), A + (size_t)(row0 + r) * K + kt + sg * 8);
        cp16(sB + sw_off(r, sg), Wt + (size_t)(col0 + r) * K + kt + sg * 8);
    }
    asm volatile("cp.async.commit_group;");
}

template <int K>
__device__ __forceinline__ void gemm_body(const __half* __restrict__ A,
                                          const __half* __restrict__ Wt,
                                          const float* __restrict__ bias,
                                          const __half* __restrict__ resid,
                                          __half* __restrict__ Ch,
                                          int M, int relu, int colt, int rowt,
                                          char* gsm)
{
    uint32_t sbase = smem_u32(gsm);
    int tid = threadIdx.x, lane = tid & 31, warp = tid >> 5;
    int wm = warp >> 2, wn = warp & 3;
    int gid = lane >> 2, tg = lane & 3;
    int j = lane >> 3, rr = lane & 7;
    int col0 = colt * 128, row0 = rowt * 128;

    float acc[4][4][4];
#pragma unroll
    for (int a = 0; a < 4; a++)
#pragma unroll
        for (int b = 0; b < 4; b++)
#pragma unroll
            for (int c = 0; c < 4; c++) acc[a][b][c] = 0.0f;

    constexpr int nch = K >> 6;
    load_chunk<K>(sbase, A, Wt, row0, col0, tid, 0, 0);
    load_chunk<K>(sbase, A, Wt, row0, col0, tid, 1, 64);

#pragma unroll 2
    for (int it = 0; it < nch; it++) {
        if (it + 1 < nch) asm volatile("cp.async.wait_group 1;");
        else              asm volatile("cp.async.wait_group 0;");
        __syncthreads();
        if (it + 2 < nch)
            load_chunk<K>(sbase, A, Wt, row0, col0, tid, (it + 2) % 3, (it + 2) * 64);
        uint32_t sA = sbase + (uint32_t)(it % 3) * 32768u;
        uint32_t sB = sA + 16384u;
#pragma unroll
        for (int ks = 0; ks < 4; ks++) {
            uint32_t a[4][4], bfr[2][4];
#pragma unroll
            for (int mt = 0; mt < 4; mt++)
                ldsm4(a[mt][0], a[mt][1], a[mt][2], a[mt][3],
                      sA + sw_off(wm * 64 + mt * 16 + (j & 1) * 8 + rr, ks * 2 + (j >> 1)));
#pragma unroll
            for (int p = 0; p < 2; p++)
                ldsm4(bfr[p][0], bfr[p][1], bfr[p][2], bfr[p][3],
                      sB + sw_off(wn * 32 + p * 16 + (j >> 1) * 8 + rr, ks * 2 + (j & 1)));
#pragma unroll
            for (int mt = 0; mt < 4; mt++)
#pragma unroll
                for (int nt = 0; nt < 4; nt++)
                    mma16816(acc[mt][nt], a[mt], &bfr[nt >> 1][(nt & 1) * 2]);
        }
    }

#pragma unroll
    for (int mt = 0; mt < 4; mt++)
#pragma unroll
        for (int nt = 0; nt < 4; nt++) {
            int r0 = row0 + wm * 64 + mt * 16 + gid;
            int c0 = col0 + wn * 32 + nt * 8 + tg * 2;
            float b0 = bias[c0], b1 = bias[c0 + 1];
            float v0 = acc[mt][nt][0] + b0, v1 = acc[mt][nt][1] + b1;
            float v2 = acc[mt][nt][2] + b0, v3 = acc[mt][nt][3] + b1;
            if (resid) {
                float2 ra = __half22float2(*(const __half2*)(resid + (size_t)r0 * M + c0));
                float2 rb = __half22float2(*(const __half2*)(resid + (size_t)(r0 + 8) * M + c0));
                v0 += ra.x; v1 += ra.y; v2 += rb.x; v3 += rb.y;
            }
            if (relu) {
                v0 = fmaxf(v0, 0.f); v1 = fmaxf(v1, 0.f);
                v2 = fmaxf(v2, 0.f); v3 = fmaxf(v3, 0.f);
            }
            *(__half2*)(Ch + (size_t)r0 * M + c0)       = __floats2half2_rn(v0, v1);
            *(__half2*)(Ch + (size_t)(r0 + 8) * M + c0) = __floats2half2_rn(v2, v3);
        }
}

template <int K>
__global__ void __launch_bounds__(256, 2)
gemm_std(const __half* __restrict__ A, const __half* __restrict__ Wt,
         const float* __restrict__ bias, const __half* __restrict__ resid,
         __half* __restrict__ Ch, int M, int relu)
{
    extern __shared__ char gsm[];
    gemm_body<K>(A, Wt, bias, resid, Ch, M, relu, blockIdx.x, blockIdx.y, gsm);
}

// ---------------- flash attention: 128 q-rows per CTA, 8 warps --------------
#define AT_SMEM (16384 + 2 * 16384)

__global__ void __launch_bounds__(256, 2)
attn16_kernel(const __half* __restrict__ Qg, int ldq,
              const __half* __restrict__ Kg, const __half* __restrict__ Vg, int ldkv,
              __half* __restrict__ Og)
{
    extern __shared__ __align__(128) char asmem[];
    uint32_t sbase = smem_u32(asmem);
    uint32_t sQ = sbase;
    int tid = threadIdx.x, lane = tid & 31, w = tid >> 5;
    int gid = lane >> 2, tg = lane & 3;
    int j = lane >> 3, rr = lane & 7;

    int bid = blockIdx.x;
    int qt = (bid & 1) ^ 1;            // heavy tiles first
    int h = (bid >> 1) % HH, b = bid / (2 * HH);
    int t0 = qt * 128;
    int hoff = h * HSS;

    const __half* qrow = Qg + (size_t)(b * TT + t0) * ldq + hoff;
#pragma unroll
    for (int i = 0; i < 4; i++) {
        int li = tid + i * 256; int r = li >> 3, sg = li & 7;
        cp16(sQ + sw_off(r, sg), qrow + (size_t)r * ldq + sg * 8);
    }
#define KVLOAD(ut, bufi)                                                           \
    {                                                                              \
        uint32_t sK_ = sbase + 16384u + (uint32_t)(bufi) * 16384u;                 \
        uint32_t sV_ = sK_ + 8192u;                                                \
        const __half* kr = Kg + (size_t)(b * TT + (ut) * 64) * ldkv + hoff;        \
        const __half* vr = Vg + (size_t)(b * TT + (ut) * 64) * ldkv + hoff;        \
        _Pragma("unroll")                                                          \
        for (int i = 0; i < 2; i++) {                                              \
            int li = tid + i * 256; int r = li >> 3, sg = li & 7;                  \
            cp16(sK_ + sw_off(r, sg), kr + (size_t)r * ldkv + sg * 8);             \
            cp16(sV_ + sw_off(r, sg), vr + (size_t)r * ldkv + sg * 8);             \
        }                                                                          \
        asm volatile("cp.async.commit_group;");                                    \
    }
    KVLOAD(0, 0);
    asm volatile("cp.async.wait_group 0;");
    __syncthreads();

    uint32_t qf[4][4];
#pragma unroll
    for (int ks = 0; ks < 4; ks++)
        ldsm4(qf[ks][0], qf[ks][1], qf[ks][2], qf[ks][3],
              sQ + sw_off(w * 16 + (j & 1) * 8 + rr, ks * 2 + (j >> 1)));

    float o[8][4];
#pragma unroll
    for (int nt = 0; nt < 8; nt++)
#pragma unroll
        for (int e = 0; e < 4; e++) o[nt][e] = 0.0f;
    float m0 = -1e30f, m1 = -1e30f, l0 = 0.0f, l1 = 0.0f;

    int nkv = 2 * (qt + 1);
    int r0g = t0 + w * 16 + gid;
    for (int ut = 0; ut < nkv; ut++) {
        if (ut > 0) { asm volatile("cp.async.wait_group 0;"); __syncthreads(); }
        if (ut < nkv - 1) KVLOAD(ut + 1, (ut + 1) & 1);
        uint32_t sK = sbase + 16384u + (uint32_t)(ut & 1) * 16384u;
        uint32_t sV = sK + 8192u;

        float s[8][4];
#pragma unroll
        for (int nt = 0; nt < 8; nt++)
#pragma unroll
            for (int e = 0; e < 4; e++) s[nt][e] = 0.0f;
#pragma unroll
        for (int ks = 0; ks < 4; ks++) {
            uint32_t kb[4][4];
#pragma unroll
            for (int p = 0; p < 4; p++)
                ldsm4(kb[p][0], kb[p][1], kb[p][2], kb[p][3],
                      sK + sw_off(p * 16 + (j >> 1) * 8 + rr, ks * 2 + (j & 1)));
#pragma unroll
            for (int nt = 0; nt < 8; nt++)
                mma16816(s[nt], qf[ks], &kb[nt >> 1][(nt & 1) * 2]);
        }
        if (ut >= 2 * qt) {
#pragma unroll
            for (int nt = 0; nt < 8; nt++) {
                int u0 = ut * 64 + nt * 8 + tg * 2;
                if (u0     > r0g)     s[nt][0] = -1e30f;
                if (u0 + 1 > r0g)     s[nt][1] = -1e30f;
                if (u0     > r0g + 8) s[nt][2] = -1e30f;
                if (u0 + 1 > r0g + 8) s[nt][3] = -1e30f;
            }
        }
        float mx0 = -1e30f, mx1 = -1e30f;
#pragma unroll
        for (int nt = 0; nt < 8; nt++) {
            mx0 = fmaxf(mx0, fmaxf(s[nt][0], s[nt][1]));
            mx1 = fmaxf(mx1, fmaxf(s[nt][2], s[nt][3]));
        }
        mx0 = fmaxf(mx0, __shfl_xor_sync(~0u, mx0, 1));
        mx0 = fmaxf(mx0, __shfl_xor_sync(~0u, mx0, 2));
        mx1 = fmaxf(mx1, __shfl_xor_sync(~0u, mx1, 1));
        mx1 = fmaxf(mx1, __shfl_xor_sync(~0u, mx1, 2));
        float mn0 = fmaxf(m0, mx0), mn1 = fmaxf(m1, mx1);
        float f0 = __expf(m0 - mn0), f1 = __expf(m1 - mn1);
        m0 = mn0; m1 = mn1;
        float rs0 = 0.0f, rs1 = 0.0f;
#pragma unroll
        for (int nt = 0; nt < 8; nt++) {
            s[nt][0] = __expf(s[nt][0] - mn0); rs0 += s[nt][0];
            s[nt][1] = __expf(s[nt][1] - mn0); rs0 += s[nt][1];
            s[nt][2] = __expf(s[nt][2] - mn1); rs1 += s[nt][2];
            s[nt][3] = __expf(s[nt][3] - mn1); rs1 += s[nt][3];
        }
        rs0 += __shfl_xor_sync(~0u, rs0, 1); rs0 += __shfl_xor_sync(~0u, rs0, 2);
        rs1 += __shfl_xor_sync(~0u, rs1, 1); rs1 += __shfl_xor_sync(~0u, rs1, 2);
        l0 = l0 * f0 + rs0;
        l1 = l1 * f1 + rs1;
#pragma unroll
        for (int nt = 0; nt < 8; nt++) {
            o[nt][0] *= f0; o[nt][1] *= f0; o[nt][2] *= f1; o[nt][3] *= f1;
        }
        uint32_t pa[4][4];
#pragma unroll
        for (int kk = 0; kk < 4; kk++) {
            pa[kk][0] = ph2(s[2 * kk][0], s[2 * kk][1]);
            pa[kk][1] = ph2(s[2 * kk][2], s[2 * kk][3]);
            pa[kk][2] = ph2(s[2 * kk + 1][0], s[2 * kk + 1][1]);
            pa[kk][3] = ph2(s[2 * kk + 1][2], s[2 * kk + 1][3]);
        }
#pragma unroll
        for (int kk = 0; kk < 4; kk++) {
            uint32_t vb[4][4];
#pragma unroll
            for (int p = 0; p < 4; p++)
                ldsm4t(vb[p][0], vb[p][1], vb[p][2], vb[p][3],
                       sV + sw_off(kk * 16 + (j & 1) * 8 + rr, p * 2 + (j >> 1)));
#pragma unroll
            for (int nt = 0; nt < 8; nt++)
                mma16816(o[nt], pa[kk], &vb[nt >> 1][(nt & 1) * 2]);
        }
    }
    float i0 = 1.0f / l0, i1 = 1.0f / l1;
    __half* orow = Og + (size_t)(b * TT + t0) * EE + hoff;
#pragma unroll
    for (int nt = 0; nt < 8; nt++) {
        int c = nt * 8 + tg * 2;
        *(__half2*)(orow + (size_t)(w * 16 + gid) * EE + c) =
            __floats2half2_rn(o[nt][0] * i0, o[nt][1] * i0);
        *(__half2*)(orow + (size_t)(w * 16 + gid + 8) * EE + c) =
            __floats2half2_rn(o[nt][2] * i1, o[nt][3] * i1);
    }
}

// ---------------- LayerNorm: fp16 in, one warp per row, shuffle-only --------
__global__ void __launch_bounds__(256)
ln_kernel(const __half* __restrict__ s_in,
          const float* __restrict__ g, const float* __restrict__ bt,
          __half* __restrict__ oh, float* __restrict__ of) {
    int warp = threadIdx.x >> 5, lane = threadIdx.x & 31;
    int row = blockIdx.x * 8 + warp;
    const uint2* rp = (const uint2*)(s_in + (size_t)row * EE);
    float v[3][4];
#pragma unroll
    for (int i = 0; i < 3; i++) {
        uint2 raw = rp[lane + 32 * i];
        float2 f0 = __half22float2(*reinterpret_cast<__half2*>(&raw.x));
        float2 f1 = __half22float2(*reinterpret_cast<__half2*>(&raw.y));
        v[i][0] = f0.x; v[i][1] = f0.y; v[i][2] = f1.x; v[i][3] = f1.y;
    }
    float s = 0.0f;
#pragma unroll
    for (int i = 0; i < 3; i++) s += v[i][0] + v[i][1] + v[i][2] + v[i][3];
#pragma unroll
    for (int off = 16; off; off >>= 1) s += __shfl_xor_sync(~0u, s, off);
    float mean = s * (1.0f / EE);
    float sq = 0.0f;
#pragma unroll
    for (int i = 0; i < 3; i++) {
        float a0 = v[i][0] - mean, a1 = v[i][1] - mean;
        float a2 = v[i][2] - mean, a3 = v[i][3] - mean;
        sq += a0 * a0 + a1 * a1 + a2 * a2 + a3 * a3;
    }
#pragma unroll
    for (int off = 16; off; off >>= 1) sq += __shfl_xor_sync(~0u, sq, off);
    float inv = rsqrtf(sq * (1.0f / EE) + 1e-5f);
    uint2* ohp = oh ? (uint2*)(oh + (size_t)row * EE) : nullptr;
    float4* ofp = of ? (float4*)(of + (size_t)row * EE) : nullptr;
#pragma unroll
    for (int i = 0; i < 3; i++) {
        int e4 = lane + 32 * i;
        float4 gg = *(const float4*)(g + e4 * 4);
        float4 bb = *(const float4*)(bt + e4 * 4);
        float r0 = (v[i][0] - mean) * inv * gg.x + bb.x;
        float r1 = (v[i][1] - mean) * inv * gg.y + bb.y;
        float r2 = (v[i][2] - mean) * inv * gg.z + bb.z;
        float r3 = (v[i][3] - mean) * inv * gg.w + bb.w;
        if (ohp) {
            uint2 pk;
            pk.x = ph2(r0, r1);
            pk.y = ph2(r2, r3);
            ohp[e4] = pk;
        }
        if (ofp) ofp[e4] = make_float4(r0, r1, r2, r3);
    }
}

// ---------------- host orchestration ---------------------------------------
extern "C" void kernel_launch(void* const* d_in, const int* in_sizes, int n_in,
                              void* d_out, int out_size) {
    const float* enc = (const float*)d_in[0];
    const float* x   = (const float*)d_in[1];
    const float* sa1_wq = (const float*)d_in[2];
    const float* sa1_bq = (const float*)d_in[3];
    const float* sa1_wk = (const float*)d_in[4];
    const float* sa1_bk = (const float*)d_in[5];
    const float* sa1_wv = (const float*)d_in[6];
    const float* sa1_bv = (const float*)d_in[7];
    const float* sa1_pw = (const float*)d_in[8];
    const float* sa1_pb = (const float*)d_in[9];
    const float* sa2_wq = (const float*)d_in[10];
    const float* sa2_bq = (const float*)d_in[11];
    const float* sa2_wk = (const float*)d_in[12];
    const float* sa2_bk = (const float*)d_in[13];
    const float* sa2_wv = (const float*)d_in[14];
    const float* sa2_bv = (const float*)d_in[15];
    const float* sa2_pw = (const float*)d_in[16];
    const float* sa2_pb = (const float*)d_in[17];
    const float* ff_w1  = (const float*)d_in[18];
    const float* ff_b1  = (const float*)d_in[19];
    const float* ff_w2  = (const float*)d_in[20];
    const float* ff_b2  = (const float*)d_in[21];
    const float* ln1_g  = (const float*)d_in[22];
    const float* ln1_b  = (const float*)d_in[23];
    const float* ln2_g  = (const float*)d_in[24];
    const float* ln2_b  = (const float*)d_in[25];
    const float* ln3_g  = (const float*)d_in[26];
    const float* ln3_b  = (const float*)d_in[27];
    float* out = (float*)d_out;

    // lazy-init side stream + events (first call is uncaptured)
    static cudaStream_t s_aux = nullptr;
    static cudaEvent_t evFork = nullptr, evActs = nullptr, evW = nullptr, evKV = nullptr;
    if (!s_aux) {
        cudaStreamCreateWithFlags(&s_aux, cudaStreamNonBlocking);
        cudaEventCreateWithFlags(&evFork, cudaEventDisableTiming);
        cudaEventCreateWithFlags(&evActs, cudaEventDisableTiming);
        cudaEventCreateWithFlags(&evW,    cudaEventDisableTiming);
        cudaEventCreateWithFlags(&evKV,   cudaEventDisableTiming);
        cudaFuncSetAttribute(gemm_std<384>,
                             cudaFuncAttributeMaxDynamicSharedMemorySize, G16_SMEM);
        cudaFuncSetAttribute(gemm_std<1536>,
                             cudaFuncAttributeMaxDynamicSharedMemorySize, G16_SMEM);
        cudaFuncSetAttribute(attn16_kernel,
                             cudaFuncAttributeMaxDynamicSharedMemorySize, AT_SMEM);
    }

    __half *pqkv, *pkv, *pq, *patt, *phid, *pxh, *pench, *po1h, *po2h, *pbufh;
    __half *pwqkv, *pwq2, *pwkv, *pwp1, *pwp2, *pwf1, *pwf2;
    float *pbqkv, *pbkv, *pbq2;
    cudaGetSymbolAddress((void**)&pqkv,  g_qkv_h);
    cudaGetSymbolAddress((void**)&pkv,   g_kv_h);
    cudaGetSymbolAddress((void**)&pq,    g_q_h);
    cudaGetSymbolAddress((void**)&patt,  g_att_h);
    cudaGetSymbolAddress((void**)&phid,  g_hid_h);
    cudaGetSymbolAddress((void**)&pxh,   g_xh);
    cudaGetSymbolAddress((void**)&pench, g_ench);
    cudaGetSymbolAddress((void**)&po1h,  g_po1h);
    cudaGetSymbolAddress((void**)&po2h,  g_po2h);
    cudaGetSymbolAddress((void**)&pbufh, g_bufh);
    cudaGetSymbolAddress((void**)&pwqkv, g_wqkvh);
    cudaGetSymbolAddress((void**)&pwq2,  g_wq2h);
    cudaGetSymbolAddress((void**)&pwkv,  g_wkvh);
    cudaGetSymbolAddress((void**)&pwp1,  g_wp1h);
    cudaGetSymbolAddress((void**)&pwp2,  g_wp2h);
    cudaGetSymbolAddress((void**)&pwf1,  g_wf1h);
    cudaGetSymbolAddress((void**)&pwf2,  g_wf2h);
    cudaGetSymbolAddress((void**)&pbqkv, g_bqkv);
    cudaGetSymbolAddress((void**)&pbkv,  g_bkv);
    cudaGetSymbolAddress((void**)&pbq2,  g_bq2);

    // fork aux stream at entry
    cudaEventRecord(evFork, 0);
    cudaStreamWaitEvent(s_aux, evFork, 0);

    // aux: off-critical-path weight transposes
    packB_kernel<<<PB_TOTAL, 256, 0, s_aux>>>(
        sa2_wq, sa1_pw, sa2_pw, ff_w1, ff_w2,
        pwq2, pwp1, pwp2, pwf1, pwf2);
    cudaEventRecord(evW, s_aux);

    // main: critical-path pack (acts, qkv/kv weights, biases)
    packA_kernel<<<PA_TOTAL, 256>>>(
        sa1_wq, sa1_wk, sa1_wv, sa2_wk, sa2_wv,
        sa1_bq, sa1_bk, sa1_bv, sa2_bq, sa2_bk, sa2_bv,
        x, enc,
        pwqkv, pwkv, pbqkv, pbkv, pbq2, pxh, pench);
    cudaEventRecord(evActs, 0);

    // aux: KV(enc) projection — needed only at attn2
    cudaStreamWaitEvent(s_aux, evActs, 0);
    gemm_std<384><<<dim3(6, 128), 256, G16_SMEM, s_aux>>>(
        pench, pwkv, pbkv, nullptr, pkv, 2 * EE, 0);
    cudaEventRecord(evKV, s_aux);

    // main: QKV(x) projection + attn1
    gemm_std<384><<<dim3(9, 128), 256, G16_SMEM>>>(
        pxh, pwqkv, pbqkv, nullptr, pqkv, 3 * EE, 0);
    attn16_kernel<<<BB * HH * 2, 256, AT_SMEM>>>(pqkv, 3 * EE,
                                                 pqkv + EE, pqkv + 2 * EE, 3 * EE, patt);

    // join packB before first use of proj weights
    cudaStreamWaitEvent(0, evW, 0);
    gemm_std<384><<<dim3(3, 128), 256, G16_SMEM>>>(
        patt, pwp1, sa1_pb, pxh, pbufh, EE, 0);                 // bufh = x + proj
    ln_kernel<<<NROWS / 8, 256>>>(pbufh, ln1_g, ln1_b, po1h, nullptr);

    // block 2: q-proj; join KV before attn2
    gemm_std<384><<<dim3(3, 128), 256, G16_SMEM>>>(
        po1h, pwq2, pbq2, nullptr, pq, EE, 0);
    cudaStreamWaitEvent(0, evKV, 0);
    attn16_kernel<<<BB * HH * 2, 256, AT_SMEM>>>(pq, EE,
                                                 pkv, pkv + EE, 2 * EE, patt);
    gemm_std<384><<<dim3(3, 128), 256, G16_SMEM>>>(
        patt, pwp2, sa2_pb, po1h, pbufh, EE, 0);                // bufh = o1 + proj
    ln_kernel<<<NROWS / 8, 256>>>(pbufh, ln2_g, ln2_b, po2h, nullptr);

    // FFN + add&norm
    gemm_std<384><<<dim3(12, 128), 256, G16_SMEM>>>(
        po2h, pwf1, ff_b1, nullptr, phid, FFD, 1);
    gemm_std<1536><<<dim3(3, 128), 256, G16_SMEM>>>(
        phid, pwf2, ff_b2, po2h, pbufh, EE, 0);                 // bufh = o2 + ff
    ln_kernel<<<NROWS / 8, 256>>>(pbufh, ln3_g, ln3_b, nullptr, out);
}